// round 11
// baseline (speedup 1.0000x reference)
#include <cuda_runtime.h>
#include <cuda_fp16.h>
#include <math.h>

#define DIMC   128
#define HEADS  8
#define HD     16
#define DD     5
#define HH     24
#define WWID   48
#define NP     (DD*HH*WWID)   /* 5760 */
#define NH     576            /* padded halo rows (560 real) */
#define NREAL  560
#define RS2    72             /* attn KV row stride in halves (144B) */
#define GS2    72             /* qkv gemm smem row stride in halves */
#define GS3    136            /* proj gemm smem row stride (K=128 + pad) */

#define LOG2E      1.4426950408889634f
#define SHIFT2     5.7707801635558535f   /* 4*log2e */

typedef unsigned int u32;

// Scratch
__device__ __half g_xh[NP * DIMC],  g_xl[NP * DIMC];
__device__ __half g_wqh[384 * 128], g_wql[384 * 128];
__device__ __half g_wph[128 * 128], g_wpl[128 * 128];
__device__ __half g_qh[NP * DIMC];
__device__ __half g_kh[NP * DIMC];
__device__ __half g_vh[NP * DIMC];
__device__ float  g_att[NP * DIMC];

// ---------------------------------------------------------------------------
// helpers
// ---------------------------------------------------------------------------
__device__ __forceinline__ u32 smaddr(const void* p) { return (u32)__cvta_generic_to_shared(p); }

__device__ __forceinline__ void ldsm_x4(u32& r0, u32& r1, u32& r2, u32& r3, u32 a) {
    asm volatile("ldmatrix.sync.aligned.m8n8.x4.shared.b16 {%0,%1,%2,%3},[%4];"
                 : "=r"(r0), "=r"(r1), "=r"(r2), "=r"(r3) : "r"(a));
}
__device__ __forceinline__ void ldsm_x2(u32& r0, u32& r1, u32 a) {
    asm volatile("ldmatrix.sync.aligned.m8n8.x2.shared.b16 {%0,%1},[%2];"
                 : "=r"(r0), "=r"(r1) : "r"(a));
}
__device__ __forceinline__ void ldsm_x4_t(u32& r0, u32& r1, u32& r2, u32& r3, u32 a) {
    asm volatile("ldmatrix.sync.aligned.m8n8.x4.trans.shared.b16 {%0,%1,%2,%3},[%4];"
                 : "=r"(r0), "=r"(r1), "=r"(r2), "=r"(r3) : "r"(a));
}
__device__ __forceinline__ void ldsm_x2_t(u32& r0, u32& r1, u32 a) {
    asm volatile("ldmatrix.sync.aligned.m8n8.x2.trans.shared.b16 {%0,%1},[%2];"
                 : "=r"(r0), "=r"(r1) : "r"(a));
}
__device__ __forceinline__ void mma16816(float* d, u32 a0, u32 a1, u32 a2, u32 a3, u32 b0, u32 b1) {
    asm volatile("mma.sync.aligned.m16n8k16.row.col.f32.f16.f16.f32 "
                 "{%0,%1,%2,%3},{%4,%5,%6,%7},{%8,%9},{%0,%1,%2,%3};"
                 : "+f"(d[0]), "+f"(d[1]), "+f"(d[2]), "+f"(d[3])
                 : "r"(a0), "r"(a1), "r"(a2), "r"(a3), "r"(b0), "r"(b1));
}
__device__ __forceinline__ void mma1688(float* d, u32 a0, u32 a1, u32 b0) {
    asm volatile("mma.sync.aligned.m16n8k8.row.col.f32.f16.f16.f32 "
                 "{%0,%1,%2,%3},{%4,%5},{%6},{%0,%1,%2,%3};"
                 : "+f"(d[0]), "+f"(d[1]), "+f"(d[2]), "+f"(d[3])
                 : "r"(a0), "r"(a1), "r"(b0));
}
__device__ __forceinline__ u32 packh2(float x, float y) {
    __half2 h = __floats2half2_rn(x, y);
    return *(u32*)&h;
}
__device__ __forceinline__ u32 ex2h2(u32 x) {
    u32 r;
    asm("ex2.approx.f16x2 %0, %1;" : "=r"(r) : "r"(x));
    return r;
}
__device__ __forceinline__ void split2(float x, float y, u32& hi, u32& lo) {
    __half hx = __float2half_rn(x), hy = __float2half_rn(y);
    __half2 h2 = __halves2half2(hx, hy);
    hi = *(u32*)&h2;
    __half2 l2 = __floats2half2_rn(x - __half2float(hx), y - __half2float(hy));
    lo = *(u32*)&l2;
}

// ---------------------------------------------------------------------------
// Prep: split x / qkv_w / proj_w into hi/lo fp16, once.
// ---------------------------------------------------------------------------
__global__ __launch_bounds__(256) void split_prep(const float* __restrict__ x,
                                                  const float* __restrict__ wq,
                                                  const float* __restrict__ wp)
{
    int i = blockIdx.x * 256 + threadIdx.x;
    const float* src;
    __half *dh, *dl;
    int off;
    if (i < 184320)      { src = x;  dh = g_xh;  dl = g_xl;  off = i; }
    else if (i < 196608) { src = wq; dh = g_wqh; dl = g_wql; off = i - 184320; }
    else if (i < 200704) { src = wp; dh = g_wph; dl = g_wpl; off = i - 196608; }
    else return;
    float4 v = ((const float4*)src)[off];
    u32 h0, l0, h1, l1;
    split2(v.x, v.y, h0, l0);
    split2(v.z, v.w, h1, l1);
    *(uint2*)(dh + off * 4) = make_uint2(h0, h1);
    *(uint2*)(dl + off * 4) = make_uint2(l0, l1);
}

// ---------------------------------------------------------------------------
// QKV GEMM (unchanged from round-10): presplit operands, 64x64, K in 2 chunks
// ---------------------------------------------------------------------------
struct SmemGemm {
    __half Ah[64 * GS2];
    __half Al[64 * GS2];
    __half Bh[64 * GS2];
    __half Bl[64 * GS2];
};

__global__ __launch_bounds__(256, 4) void gemm_qkv(const float* __restrict__ bias)
{
    extern __shared__ char smraw[];
    SmemGemm* sm = (SmemGemm*)smraw;
    const int tid = threadIdx.x, warp = tid >> 5, lane = tid & 31;
    const int bm = blockIdx.x * 64, bn = blockIdx.y * 64;

    const int wm = warp >> 1, wn = warp & 1;
    const u32 aoff  = (u32)((wm * 16 + (lane & 15)) * GS2 + (lane >> 4) * 8) * 2;
    const u32 boff0 = (u32)((wn * 32 +      (lane & 15)) * GS2 + (lane >> 4) * 8) * 2;
    const u32 boff1 = (u32)((wn * 32 + 16 + (lane & 15)) * GS2 + (lane >> 4) * 8) * 2;
    const u32 ah_b  = smaddr(sm->Ah) + aoff;
    const u32 al_b  = smaddr(sm->Al) + aoff;
    const u32 bh_b0 = smaddr(sm->Bh) + boff0, bh_b1 = smaddr(sm->Bh) + boff1;
    const u32 bl_b0 = smaddr(sm->Bl) + boff0, bl_b1 = smaddr(sm->Bl) + boff1;

    float acc[4][4] = {};

    for (int k0 = 0; k0 < 128; k0 += 64) {
        if (k0) __syncthreads();
#pragma unroll
        for (int t = 0; t < 2; t++) {
            int e = tid + t * 256;
            int row = e >> 3, c = e & 7;
            int gcol = k0 + c * 8;
            *(uint4*)(sm->Ah + row * GS2 + c * 8) = *(const uint4*)(g_xh  + (size_t)(bm + row) * 128 + gcol);
            *(uint4*)(sm->Al + row * GS2 + c * 8) = *(const uint4*)(g_xl  + (size_t)(bm + row) * 128 + gcol);
            *(uint4*)(sm->Bh + row * GS2 + c * 8) = *(const uint4*)(g_wqh + (size_t)(bn + row) * 128 + gcol);
            *(uint4*)(sm->Bl + row * GS2 + c * 8) = *(const uint4*)(g_wql + (size_t)(bn + row) * 128 + gcol);
        }
        __syncthreads();

#pragma unroll
        for (int ks = 0; ks < 4; ks++) {
            const u32 kb = ks * 32;
            u32 ah0, ah1, ah2, ah3;
            u32 b0, b1, b2, b3, b4, b5, b6, b7;
            ldsm_x4(ah0, ah1, ah2, ah3, ah_b + kb);
            ldsm_x4(b0, b1, b2, b3, bh_b0 + kb);
            ldsm_x4(b4, b5, b6, b7, bh_b1 + kb);
            mma16816(acc[0], ah0, ah1, ah2, ah3, b0, b2);
            mma16816(acc[1], ah0, ah1, ah2, ah3, b1, b3);
            mma16816(acc[2], ah0, ah1, ah2, ah3, b4, b6);
            mma16816(acc[3], ah0, ah1, ah2, ah3, b5, b7);
            {
                u32 al0, al1, al2, al3;
                ldsm_x4(al0, al1, al2, al3, al_b + kb);
                mma16816(acc[0], al0, al1, al2, al3, b0, b2);
                mma16816(acc[1], al0, al1, al2, al3, b1, b3);
                mma16816(acc[2], al0, al1, al2, al3, b4, b6);
                mma16816(acc[3], al0, al1, al2, al3, b5, b7);
            }
            ldsm_x4(b0, b1, b2, b3, bl_b0 + kb);
            ldsm_x4(b4, b5, b6, b7, bl_b1 + kb);
            mma16816(acc[0], ah0, ah1, ah2, ah3, b0, b2);
            mma16816(acc[1], ah0, ah1, ah2, ah3, b1, b3);
            mma16816(acc[2], ah0, ah1, ah2, ah3, b4, b6);
            mma16816(acc[3], ah0, ah1, ah2, ah3, b5, b7);
        }
    }

    const int r0 = bm + wm * 16 + (lane >> 2);
    const int r1 = r0 + 8;
#pragma unroll
    for (int nt = 0; nt < 4; nt++) {
        const int cg = bn + wn * 32 + nt * 8 + 2 * (lane & 3);
        const float b0v = bias[cg], b1v = bias[cg + 1];
        float v00 = acc[nt][0] + b0v, v01 = acc[nt][1] + b1v;
        float v10 = acc[nt][2] + b0v, v11 = acc[nt][3] + b1v;
        const int seg = cg >> 7;
        const int lc  = cg - seg * 128;
        __half* base = (seg == 0) ? g_qh : (seg == 1) ? g_kh : g_vh;
        if (seg == 0) {
            const float qs = 0.25f * LOG2E;
            v00 *= qs; v01 *= qs; v10 *= qs; v11 *= qs;
        }
        *(__half2*)(base + (size_t)r0 * DIMC + lc) = __floats2half2_rn(v00, v01);
        *(__half2*)(base + (size_t)r1 * DIMC + lc) = __floats2half2_rn(v10, v11);
    }
}

// ---------------------------------------------------------------------------
// Proj GEMM v2: 32x64 tile, 128 threads, K=128 single pass -> 360 blocks.
// A = g_att fp32 split in-block; B presplit.
// ---------------------------------------------------------------------------
struct SmemProj {
    __half Ah[32 * GS3];
    __half Al[32 * GS3];
    __half Bh[64 * GS3];
    __half Bl[64 * GS3];
};

__global__ __launch_bounds__(128, 4) void gemm_proj(const float* __restrict__ A,
                                                    const float* __restrict__ bias,
                                                    float* __restrict__ Cout)
{
    extern __shared__ char smraw[];
    SmemProj* sm = (SmemProj*)smraw;
    const int tid = threadIdx.x, warp = tid >> 5, lane = tid & 31;
    const int bm = blockIdx.x * 32, bn = blockIdx.y * 64;

    // ---- load: A 32x128 fp32 split; B 64x128 presplit copy ----
    {
        const int row = tid >> 2, q = tid & 3;       // 32 rows x 4 col-quarters
        const float* Ar = A + (size_t)(bm + row) * 128 + q * 32;
        __half* ah = sm->Ah + row * GS3 + q * 32;
        __half* al = sm->Al + row * GS3 + q * 32;
#pragma unroll
        for (int j = 0; j < 8; j++) {
            float4 v = *(const float4*)(Ar + j * 4);
            u32 h0, l0, h1, l1;
            split2(v.x, v.y, h0, l0);
            split2(v.z, v.w, h1, l1);
            *(uint2*)(ah + j * 4) = make_uint2(h0, h1);
            *(uint2*)(al + j * 4) = make_uint2(l0, l1);
        }
#pragma unroll
        for (int t = 0; t < 8; t++) {
            int e = tid + t * 128;                   // 0..1023
            int rowb = e >> 4, c = e & 15;           // 64 rows x 16 uint4
            *(uint4*)(sm->Bh + rowb * GS3 + c * 8) = *(const uint4*)(g_wph + (size_t)(bn + rowb) * 128 + c * 8);
            *(uint4*)(sm->Bl + rowb * GS3 + c * 8) = *(const uint4*)(g_wpl + (size_t)(bn + rowb) * 128 + c * 8);
        }
    }
    __syncthreads();

    // ---- mainloop: 4 warps, warp = (wm, wn) over (2 x 2), 16x32 per warp ----
    const int wm = warp >> 1, wn = warp & 1;
    const u32 aoff  = (u32)((wm * 16 + (lane & 15)) * GS3 + (lane >> 4) * 8) * 2;
    const u32 boff0 = (u32)((wn * 32 +      (lane & 15)) * GS3 + (lane >> 4) * 8) * 2;
    const u32 boff1 = (u32)((wn * 32 + 16 + (lane & 15)) * GS3 + (lane >> 4) * 8) * 2;
    const u32 ah_b  = smaddr(sm->Ah) + aoff;
    const u32 al_b  = smaddr(sm->Al) + aoff;
    const u32 bh_b0 = smaddr(sm->Bh) + boff0, bh_b1 = smaddr(sm->Bh) + boff1;
    const u32 bl_b0 = smaddr(sm->Bl) + boff0, bl_b1 = smaddr(sm->Bl) + boff1;

    float acc[4][4] = {};
#pragma unroll
    for (int ks = 0; ks < 8; ks++) {
        const u32 kb = ks * 32;
        u32 ah0, ah1, ah2, ah3;
        u32 b0, b1, b2, b3, b4, b5, b6, b7;
        ldsm_x4(ah0, ah1, ah2, ah3, ah_b + kb);
        ldsm_x4(b0, b1, b2, b3, bh_b0 + kb);
        ldsm_x4(b4, b5, b6, b7, bh_b1 + kb);
        mma16816(acc[0], ah0, ah1, ah2, ah3, b0, b2);
        mma16816(acc[1], ah0, ah1, ah2, ah3, b1, b3);
        mma16816(acc[2], ah0, ah1, ah2, ah3, b4, b6);
        mma16816(acc[3], ah0, ah1, ah2, ah3, b5, b7);
        {
            u32 al0, al1, al2, al3;
            ldsm_x4(al0, al1, al2, al3, al_b + kb);
            mma16816(acc[0], al0, al1, al2, al3, b0, b2);
            mma16816(acc[1], al0, al1, al2, al3, b1, b3);
            mma16816(acc[2], al0, al1, al2, al3, b4, b6);
            mma16816(acc[3], al0, al1, al2, al3, b5, b7);
        }
        ldsm_x4(b0, b1, b2, b3, bl_b0 + kb);
        ldsm_x4(b4, b5, b6, b7, bl_b1 + kb);
        mma16816(acc[0], ah0, ah1, ah2, ah3, b0, b2);
        mma16816(acc[1], ah0, ah1, ah2, ah3, b1, b3);
        mma16816(acc[2], ah0, ah1, ah2, ah3, b4, b6);
        mma16816(acc[3], ah0, ah1, ah2, ah3, b5, b7);
    }

    const int r0 = bm + wm * 16 + (lane >> 2);
    const int r1 = r0 + 8;
#pragma unroll
    for (int nt = 0; nt < 4; nt++) {
        const int cg = bn + wn * 32 + nt * 8 + 2 * (lane & 3);
        const float b0v = bias[cg], b1v = bias[cg + 1];
        *(float2*)(Cout + (size_t)r0 * 128 + cg) = make_float2(acc[nt][0] + b0v, acc[nt][1] + b1v);
        *(float2*)(Cout + (size_t)r1 * 128 + cg) = make_float2(acc[nt][2] + b0v, acc[nt][3] + b1v);
    }
}

// ---------------------------------------------------------------------------
// Attention v4: fp16x2 exp, bit-AND masking, row sums via mma against ones.
// ---------------------------------------------------------------------------
struct SmemAttn {
    __half KV[NH * RS2];
    __half Qs[10][16][24];
    int    rowmap[NH];
    unsigned short vmask[NH];
};

__global__ __launch_bounds__(320) void attn_mma(void)
{
    extern __shared__ char smraw[];
    SmemAttn* sm = (SmemAttn*)smraw;

    const int tid  = threadIdx.x;
    const int warp = tid >> 5;
    const int lane = tid & 31;

    const int hp   = blockIdx.x & 3;
    const int tile = blockIdx.x >> 2;
    const int tw   = tile % 6;
    const int th   = tile / 6;
    const int hy0  = th * 2;
    const int wx0  = tw * 8;

    const int hl   = warp / 5;
    const int dt   = warp % 5;
    const int head = hp * 2 + hl;

#pragma unroll
    for (int t = 0; t < 2; t++) {
        int rr = tid + t * 320;
        if (rr < NH) {
            int map = -1;
            unsigned vm = 0;
            if (rr < NREAL) {
                int d   = rr / 112;
                int rem = rr % 112;
                int ih  = rem / 14;
                int iw  = rem % 14;
                int h2  = (hy0 + ih + 21) % HH;
                int w2  = (wx0 + iw + 45) % WWID;
                map = (d * HH + h2) * WWID + w2;
                int wlo = iw - 6 < 0 ? 0 : iw - 6;
                int whi = iw < 7 ? iw : 7;
                unsigned wm = (whi >= wlo) ? ((0xFFu << wlo) & (0xFFu >> (7 - whi))) : 0u;
                unsigned m0 = (ih <= 6) ? wm : 0u;
                unsigned m1 = (ih >= 1) ? wm : 0u;
                vm = m0 | (m1 << 8);
            }
            sm->rowmap[rr] = map;
            sm->vmask[rr]  = (unsigned short)vm;
        }
    }
    {
        int r = lane >> 1, hf = lane & 1;
        int gp = ((dt * HH + hy0 + (r >> 3)) * WWID + wx0 + (r & 7));
        *(uint4*)&sm->Qs[warp][r][hf * 8] =
            *(const uint4*)(g_qh + (size_t)gp * DIMC + head * HD + hf * 8);
    }
    __syncthreads();

#pragma unroll
    for (int t = 0; t < 15; t++) {
        int e = tid + t * 320;
        if (e < NH * 8) {
            int row = e >> 3, c = e & 7;
            int cc  = c & 3;
            int g   = sm->rowmap[row];
            uint4 v = make_uint4(0u, 0u, 0u, 0u);
            const __half* base = (c < 4) ? g_kh : g_vh;
            if (g >= 0) v = *(const uint4*)(base + (size_t)g * DIMC + hp * 32 + cc * 8);
            *(uint4*)&sm->KV[row * RS2 + ((c < 4) ? 0 : 32) + cc * 8] = v;
        }
    }
    __syncthreads();

    const u32 qb  = smaddr(&sm->Qs[warp][0][0]);
    const u32 kvb = smaddr(sm->KV);
    const int r0  = lane >> 2;
    const u32 ones_b = (lane < 4) ? 0x3C003C00u : 0u;   // B[k][0]=1 fragment

    u32 qa0, qa1, qa2, qa3;
    {
        int l4 = lane & 15, cg = lane >> 4;
        ldsm_x4(qa0, qa1, qa2, qa3, qb + (u32)(l4 * 24 + cg * 8) * 2);
    }

    float dacc[8];
#pragma unroll
    for (int i = 0; i < 8; i++) dacc[i] = 0.f;
    float sacc[4] = {0.f, 0.f, 0.f, 0.f};

#pragma unroll
    for (int ch = 0; ch < 8; ch++) {
        const int c0 = ch * 72;
        float c[9][4];
#pragma unroll
        for (int t = 0; t < 9; t++)
            c[t][0] = c[t][1] = c[t][2] = c[t][3] = -SHIFT2;

        // QK scores (log2 domain, shift pre-loaded)
#pragma unroll
        for (int t = 0; t < 9; t++) {
            int l4 = lane & 15;
            u32 addr = kvb + (u32)((c0 + t * 8 + (l4 & 7)) * RS2 + hl * 16 + (l4 >> 3) * 8) * 2;
            u32 b0, b1;
            ldsm_x2(b0, b1, addr);
            mma16816(c[t], qa0, qa1, qa2, qa3, b0, b1);
        }

        // pack -> fp16x2 exp -> bit-AND mask; af0 = row r0 pair, af1 = row r1 pair
        u32 af0[9], af1[9];
#pragma unroll
        for (int t = 0; t < 9; t++) {
            int cA = c0 + t * 8 + 2 * (lane & 3);
            u32 mm = *(const u32*)&sm->vmask[cA];
            u32 e0 = ex2h2(packh2(c[t][0], c[t][1]));
            u32 e1 = ex2h2(packh2(c[t][2], c[t][3]));
            u32 m0 = (((mm >>  r0)       & 1u) * 0x0000FFFFu) | (((mm >> (16 + r0)) & 1u) * 0xFFFF0000u);
            u32 m1 = (((mm >> (8 + r0))  & 1u) * 0x0000FFFFu) | (((mm >> (24 + r0)) & 1u) * 0xFFFF0000u);
            af0[t] = e0 & m0;
            af1[t] = e1 & m1;
        }

        // PV accumulate + row sums (ones column) on tensor pipe
#pragma unroll
        for (int kc = 0; kc < 4; kc++) {
            u32 a0 = af0[2 * kc],     a1 = af1[2 * kc];
            u32 a2 = af0[2 * kc + 1], a3 = af1[2 * kc + 1];
            int g = lane >> 3, rr2 = lane & 7;
            int row = c0 + kc * 16 + ((g & 1) << 3) + rr2;
            u32 addr = kvb + (u32)(row * RS2 + 32 + hl * 16 + (g >> 1) * 8) * 2;
            u32 b0, b1, b2, b3;
            ldsm_x4_t(b0, b1, b2, b3, addr);
            mma16816(dacc,     a0, a1, a2, a3, b0, b1);
            mma16816(dacc + 4, a0, a1, a2, a3, b2, b3);
            mma16816(sacc,     a0, a1, a2, a3, ones_b, ones_b);
        }
        {   // tail cols c0+64..71
            u32 a0 = af0[8], a1 = af1[8];
            int l4 = lane & 15;
            int row = c0 + 64 + (l4 & 7);
            u32 addr = kvb + (u32)(row * RS2 + 32 + hl * 16 + (l4 >> 3) * 8) * 2;
            u32 b0, b1;
            ldsm_x2_t(b0, b1, addr);
            mma1688(dacc,     a0, a1, b0);
            mma1688(dacc + 4, a0, a1, b1);
            mma1688(sacc,     a0, a1, ones_b);
        }
    }

    // sacc[0]/sacc[2] hold row sums in lanes with lane%4==0 (col 0); quad-reduce
    float s0 = sacc[0], s1 = sacc[2];
    s0 += __shfl_xor_sync(0xFFFFFFFF, s0, 1);
    s0 += __shfl_xor_sync(0xFFFFFFFF, s0, 2);
    s1 += __shfl_xor_sync(0xFFFFFFFF, s1, 1);
    s1 += __shfl_xor_sync(0xFFFFFFFF, s1, 2);
    const float inv0 = 1.f / s0, inv1 = 1.f / s1;

    const int q4 = lane & 3;
    const int gp0 = ((dt * HH + hy0 + 0) * WWID + wx0 + r0);
    const int gp1 = ((dt * HH + hy0 + 1) * WWID + wx0 + r0);
    float* o0 = g_att + (size_t)gp0 * DIMC + head * HD;
    float* o1 = g_att + (size_t)gp1 * DIMC + head * HD;
    *(float2*)(o0 + 2 * q4)     = make_float2(dacc[0] * inv0, dacc[1] * inv0);
    *(float2*)(o1 + 2 * q4)     = make_float2(dacc[2] * inv1, dacc[3] * inv1);
    *(float2*)(o0 + 8 + 2 * q4) = make_float2(dacc[4] * inv0, dacc[5] * inv0);
    *(float2*)(o1 + 8 + 2 * q4) = make_float2(dacc[6] * inv1, dacc[7] * inv1);
}

// ---------------------------------------------------------------------------
extern "C" void kernel_launch(void* const* d_in, const int* in_sizes, int n_in,
                              void* d_out, int out_size)
{
    const float* x      = (const float*)d_in[0];
    const float* qkv_w  = (const float*)d_in[1];
    const float* qkv_b  = (const float*)d_in[2];
    const float* proj_w = (const float*)d_in[3];
    const float* proj_b = (const float*)d_in[4];
    float* out = (float*)d_out;

    float* att;
    cudaGetSymbolAddress((void**)&att, g_att);

    static int attr_set = 0;
    if (!attr_set) {
        cudaFuncSetAttribute(attn_mma, cudaFuncAttributeMaxDynamicSharedMemorySize,
                             (int)sizeof(SmemAttn));
        cudaFuncSetAttribute(gemm_qkv, cudaFuncAttributeMaxDynamicSharedMemorySize,
                             (int)sizeof(SmemGemm));
        cudaFuncSetAttribute(gemm_proj, cudaFuncAttributeMaxDynamicSharedMemorySize,
                             (int)sizeof(SmemProj));
        attr_set = 1;
    }

    // 0) one-shot hi/lo split of x and weights
    split_prep<<<(200704 + 255) / 256, 256>>>(x, qkv_w, proj_w);
    // 1) QKV projection (presplit fp16 TC GEMM)
    gemm_qkv<<<dim3(NP / 64, 384 / 64), 256, sizeof(SmemGemm)>>>(qkv_b);
    // 2) neighborhood attention (fp16x2 exp, mma row-sums)
    attn_mma<<<72 * 4, 320, sizeof(SmemAttn)>>>();
    // 3) output projection (32x64 tiles, 360 blocks, single K pass)
    gemm_proj<<<dim3(NP / 32, 128 / 64), 128, sizeof(SmemProj)>>>(att, proj_b, out);
}

// round 13
// speedup vs baseline: 1.0409x; 1.0409x over previous
#include <cuda_runtime.h>
#include <cuda_fp16.h>
#include <math.h>

#define DIMC   128
#define HEADS  8
#define HD     16
#define DD     5
#define HH     24
#define WWID   48
#define NP     (DD*HH*WWID)   /* 5760 */
#define NH     576            /* padded halo rows (560 real) */
#define NREAL  560
#define RS2    72             /* attn KV row stride in halves (144B) */
#define GS2    72             /* qkv gemm smem row stride in halves */
#define GS3    136            /* proj gemm smem row stride (K=128 + pad) */

#define LOG2E      1.4426950408889634f
#define SHIFT2     5.7707801635558535f   /* 4*log2e */

typedef unsigned int u32;

// Scratch
__device__ __half g_xh[NP * DIMC],  g_xl[NP * DIMC];
__device__ __half g_wqh[384 * 128], g_wql[384 * 128];
__device__ __half g_wph[128 * 128], g_wpl[128 * 128];
__device__ __half g_qh[NP * DIMC];
__device__ __half g_kh[NP * DIMC];
__device__ __half g_vh[NP * DIMC];
__device__ float  g_att[NP * DIMC];

// ---------------------------------------------------------------------------
// helpers
// ---------------------------------------------------------------------------
__device__ __forceinline__ u32 smaddr(const void* p) { return (u32)__cvta_generic_to_shared(p); }

__device__ __forceinline__ void ldsm_x4(u32& r0, u32& r1, u32& r2, u32& r3, u32 a) {
    asm volatile("ldmatrix.sync.aligned.m8n8.x4.shared.b16 {%0,%1,%2,%3},[%4];"
                 : "=r"(r0), "=r"(r1), "=r"(r2), "=r"(r3) : "r"(a));
}
__device__ __forceinline__ void ldsm_x2(u32& r0, u32& r1, u32 a) {
    asm volatile("ldmatrix.sync.aligned.m8n8.x2.shared.b16 {%0,%1},[%2];"
                 : "=r"(r0), "=r"(r1) : "r"(a));
}
__device__ __forceinline__ void ldsm_x4_t(u32& r0, u32& r1, u32& r2, u32& r3, u32 a) {
    asm volatile("ldmatrix.sync.aligned.m8n8.x4.trans.shared.b16 {%0,%1,%2,%3},[%4];"
                 : "=r"(r0), "=r"(r1), "=r"(r2), "=r"(r3) : "r"(a));
}
__device__ __forceinline__ void ldsm_x2_t(u32& r0, u32& r1, u32 a) {
    asm volatile("ldmatrix.sync.aligned.m8n8.x2.trans.shared.b16 {%0,%1},[%2];"
                 : "=r"(r0), "=r"(r1) : "r"(a));
}
__device__ __forceinline__ void mma16816(float* d, u32 a0, u32 a1, u32 a2, u32 a3, u32 b0, u32 b1) {
    asm volatile("mma.sync.aligned.m16n8k16.row.col.f32.f16.f16.f32 "
                 "{%0,%1,%2,%3},{%4,%5,%6,%7},{%8,%9},{%0,%1,%2,%3};"
                 : "+f"(d[0]), "+f"(d[1]), "+f"(d[2]), "+f"(d[3])
                 : "r"(a0), "r"(a1), "r"(a2), "r"(a3), "r"(b0), "r"(b1));
}
__device__ __forceinline__ void mma1688(float* d, u32 a0, u32 a1, u32 b0) {
    asm volatile("mma.sync.aligned.m16n8k8.row.col.f32.f16.f16.f32 "
                 "{%0,%1,%2,%3},{%4,%5},{%6},{%0,%1,%2,%3};"
                 : "+f"(d[0]), "+f"(d[1]), "+f"(d[2]), "+f"(d[3])
                 : "r"(a0), "r"(a1), "r"(b0));
}
__device__ __forceinline__ u32 packh2(float x, float y) {
    __half2 h = __floats2half2_rn(x, y);
    return *(u32*)&h;
}
__device__ __forceinline__ float ex2(float x) {
    float r;
    asm("ex2.approx.f32 %0, %1;" : "=f"(r) : "f"(x));
    return r;
}
__device__ __forceinline__ void split2(float x, float y, u32& hi, u32& lo) {
    __half hx = __float2half_rn(x), hy = __float2half_rn(y);
    __half2 h2 = __halves2half2(hx, hy);
    hi = *(u32*)&h2;
    __half2 l2 = __floats2half2_rn(x - __half2float(hx), y - __half2float(hy));
    lo = *(u32*)&l2;
}

// ---------------------------------------------------------------------------
// Prep: split x / qkv_w / proj_w into hi/lo fp16, once.
// ---------------------------------------------------------------------------
__global__ __launch_bounds__(256) void split_prep(const float* __restrict__ x,
                                                  const float* __restrict__ wq,
                                                  const float* __restrict__ wp)
{
    int i = blockIdx.x * 256 + threadIdx.x;
    const float* src;
    __half *dh, *dl;
    int off;
    if (i < 184320)      { src = x;  dh = g_xh;  dl = g_xl;  off = i; }
    else if (i < 196608) { src = wq; dh = g_wqh; dl = g_wql; off = i - 184320; }
    else if (i < 200704) { src = wp; dh = g_wph; dl = g_wpl; off = i - 196608; }
    else return;
    float4 v = ((const float4*)src)[off];
    u32 h0, l0, h1, l1;
    split2(v.x, v.y, h0, l0);
    split2(v.z, v.w, h1, l1);
    *(uint2*)(dh + off * 4) = make_uint2(h0, h1);
    *(uint2*)(dl + off * 4) = make_uint2(l0, l1);
}

// ---------------------------------------------------------------------------
// QKV GEMM (round-10): presplit operands, 64x64, K in 2 chunks
// ---------------------------------------------------------------------------
struct SmemGemm {
    __half Ah[64 * GS2];
    __half Al[64 * GS2];
    __half Bh[64 * GS2];
    __half Bl[64 * GS2];
};

__global__ __launch_bounds__(256, 4) void gemm_qkv(const float* __restrict__ bias)
{
    extern __shared__ char smraw[];
    SmemGemm* sm = (SmemGemm*)smraw;
    const int tid = threadIdx.x, warp = tid >> 5, lane = tid & 31;
    const int bm = blockIdx.x * 64, bn = blockIdx.y * 64;

    const int wm = warp >> 1, wn = warp & 1;
    const u32 aoff  = (u32)((wm * 16 + (lane & 15)) * GS2 + (lane >> 4) * 8) * 2;
    const u32 boff0 = (u32)((wn * 32 +      (lane & 15)) * GS2 + (lane >> 4) * 8) * 2;
    const u32 boff1 = (u32)((wn * 32 + 16 + (lane & 15)) * GS2 + (lane >> 4) * 8) * 2;
    const u32 ah_b  = smaddr(sm->Ah) + aoff;
    const u32 al_b  = smaddr(sm->Al) + aoff;
    const u32 bh_b0 = smaddr(sm->Bh) + boff0, bh_b1 = smaddr(sm->Bh) + boff1;
    const u32 bl_b0 = smaddr(sm->Bl) + boff0, bl_b1 = smaddr(sm->Bl) + boff1;

    float acc[4][4] = {};

    for (int k0 = 0; k0 < 128; k0 += 64) {
        if (k0) __syncthreads();
#pragma unroll
        for (int t = 0; t < 2; t++) {
            int e = tid + t * 256;
            int row = e >> 3, c = e & 7;
            int gcol = k0 + c * 8;
            *(uint4*)(sm->Ah + row * GS2 + c * 8) = *(const uint4*)(g_xh  + (size_t)(bm + row) * 128 + gcol);
            *(uint4*)(sm->Al + row * GS2 + c * 8) = *(const uint4*)(g_xl  + (size_t)(bm + row) * 128 + gcol);
            *(uint4*)(sm->Bh + row * GS2 + c * 8) = *(const uint4*)(g_wqh + (size_t)(bn + row) * 128 + gcol);
            *(uint4*)(sm->Bl + row * GS2 + c * 8) = *(const uint4*)(g_wql + (size_t)(bn + row) * 128 + gcol);
        }
        __syncthreads();

#pragma unroll
        for (int ks = 0; ks < 4; ks++) {
            const u32 kb = ks * 32;
            u32 ah0, ah1, ah2, ah3;
            u32 b0, b1, b2, b3, b4, b5, b6, b7;
            ldsm_x4(ah0, ah1, ah2, ah3, ah_b + kb);
            ldsm_x4(b0, b1, b2, b3, bh_b0 + kb);
            ldsm_x4(b4, b5, b6, b7, bh_b1 + kb);
            mma16816(acc[0], ah0, ah1, ah2, ah3, b0, b2);
            mma16816(acc[1], ah0, ah1, ah2, ah3, b1, b3);
            mma16816(acc[2], ah0, ah1, ah2, ah3, b4, b6);
            mma16816(acc[3], ah0, ah1, ah2, ah3, b5, b7);
            {
                u32 al0, al1, al2, al3;
                ldsm_x4(al0, al1, al2, al3, al_b + kb);
                mma16816(acc[0], al0, al1, al2, al3, b0, b2);
                mma16816(acc[1], al0, al1, al2, al3, b1, b3);
                mma16816(acc[2], al0, al1, al2, al3, b4, b6);
                mma16816(acc[3], al0, al1, al2, al3, b5, b7);
            }
            ldsm_x4(b0, b1, b2, b3, bl_b0 + kb);
            ldsm_x4(b4, b5, b6, b7, bl_b1 + kb);
            mma16816(acc[0], ah0, ah1, ah2, ah3, b0, b2);
            mma16816(acc[1], ah0, ah1, ah2, ah3, b1, b3);
            mma16816(acc[2], ah0, ah1, ah2, ah3, b4, b6);
            mma16816(acc[3], ah0, ah1, ah2, ah3, b5, b7);
        }
    }

    const int r0 = bm + wm * 16 + (lane >> 2);
    const int r1 = r0 + 8;
#pragma unroll
    for (int nt = 0; nt < 4; nt++) {
        const int cg = bn + wn * 32 + nt * 8 + 2 * (lane & 3);
        const float b0v = bias[cg], b1v = bias[cg + 1];
        float v00 = acc[nt][0] + b0v, v01 = acc[nt][1] + b1v;
        float v10 = acc[nt][2] + b0v, v11 = acc[nt][3] + b1v;
        const int seg = cg >> 7;
        const int lc  = cg - seg * 128;
        __half* base = (seg == 0) ? g_qh : (seg == 1) ? g_kh : g_vh;
        if (seg == 0) {
            const float qs = 0.25f * LOG2E;
            v00 *= qs; v01 *= qs; v10 *= qs; v11 *= qs;
        }
        *(__half2*)(base + (size_t)r0 * DIMC + lc) = __floats2half2_rn(v00, v01);
        *(__half2*)(base + (size_t)r1 * DIMC + lc) = __floats2half2_rn(v10, v11);
    }
}

// ---------------------------------------------------------------------------
// Proj GEMM v2 (round-11 measured winner): 32x64 tile, 128 threads, K=128.
// ---------------------------------------------------------------------------
struct SmemProj {
    __half Ah[32 * GS3];
    __half Al[32 * GS3];
    __half Bh[64 * GS3];
    __half Bl[64 * GS3];
};

__global__ __launch_bounds__(128, 4) void gemm_proj(const float* __restrict__ A,
                                                    const float* __restrict__ bias,
                                                    float* __restrict__ Cout)
{
    extern __shared__ char smraw[];
    SmemProj* sm = (SmemProj*)smraw;
    const int tid = threadIdx.x, warp = tid >> 5, lane = tid & 31;
    const int bm = blockIdx.x * 32, bn = blockIdx.y * 64;

    {
        const int row = tid >> 2, q = tid & 3;
        const float* Ar = A + (size_t)(bm + row) * 128 + q * 32;
        __half* ah = sm->Ah + row * GS3 + q * 32;
        __half* al = sm->Al + row * GS3 + q * 32;
#pragma unroll
        for (int j = 0; j < 8; j++) {
            float4 v = *(const float4*)(Ar + j * 4);
            u32 h0, l0, h1, l1;
            split2(v.x, v.y, h0, l0);
            split2(v.z, v.w, h1, l1);
            *(uint2*)(ah + j * 4) = make_uint2(h0, h1);
            *(uint2*)(al + j * 4) = make_uint2(l0, l1);
        }
#pragma unroll
        for (int t = 0; t < 8; t++) {
            int e = tid + t * 128;
            int rowb = e >> 4, c = e & 15;
            *(uint4*)(sm->Bh + rowb * GS3 + c * 8) = *(const uint4*)(g_wph + (size_t)(bn + rowb) * 128 + c * 8);
            *(uint4*)(sm->Bl + rowb * GS3 + c * 8) = *(const uint4*)(g_wpl + (size_t)(bn + rowb) * 128 + c * 8);
        }
    }
    __syncthreads();

    const int wm = warp >> 1, wn = warp & 1;
    const u32 aoff  = (u32)((wm * 16 + (lane & 15)) * GS3 + (lane >> 4) * 8) * 2;
    const u32 boff0 = (u32)((wn * 32 +      (lane & 15)) * GS3 + (lane >> 4) * 8) * 2;
    const u32 boff1 = (u32)((wn * 32 + 16 + (lane & 15)) * GS3 + (lane >> 4) * 8) * 2;
    const u32 ah_b  = smaddr(sm->Ah) + aoff;
    const u32 al_b  = smaddr(sm->Al) + aoff;
    const u32 bh_b0 = smaddr(sm->Bh) + boff0, bh_b1 = smaddr(sm->Bh) + boff1;
    const u32 bl_b0 = smaddr(sm->Bl) + boff0, bl_b1 = smaddr(sm->Bl) + boff1;

    float acc[4][4] = {};
#pragma unroll
    for (int ks = 0; ks < 8; ks++) {
        const u32 kb = ks * 32;
        u32 ah0, ah1, ah2, ah3;
        u32 b0, b1, b2, b3, b4, b5, b6, b7;
        ldsm_x4(ah0, ah1, ah2, ah3, ah_b + kb);
        ldsm_x4(b0, b1, b2, b3, bh_b0 + kb);
        ldsm_x4(b4, b5, b6, b7, bh_b1 + kb);
        mma16816(acc[0], ah0, ah1, ah2, ah3, b0, b2);
        mma16816(acc[1], ah0, ah1, ah2, ah3, b1, b3);
        mma16816(acc[2], ah0, ah1, ah2, ah3, b4, b6);
        mma16816(acc[3], ah0, ah1, ah2, ah3, b5, b7);
        {
            u32 al0, al1, al2, al3;
            ldsm_x4(al0, al1, al2, al3, al_b + kb);
            mma16816(acc[0], al0, al1, al2, al3, b0, b2);
            mma16816(acc[1], al0, al1, al2, al3, b1, b3);
            mma16816(acc[2], al0, al1, al2, al3, b4, b6);
            mma16816(acc[3], al0, al1, al2, al3, b5, b7);
        }
        ldsm_x4(b0, b1, b2, b3, bl_b0 + kb);
        ldsm_x4(b4, b5, b6, b7, bl_b1 + kb);
        mma16816(acc[0], ah0, ah1, ah2, ah3, b0, b2);
        mma16816(acc[1], ah0, ah1, ah2, ah3, b1, b3);
        mma16816(acc[2], ah0, ah1, ah2, ah3, b4, b6);
        mma16816(acc[3], ah0, ah1, ah2, ah3, b5, b7);
    }

    const int r0 = bm + wm * 16 + (lane >> 2);
    const int r1 = r0 + 8;
#pragma unroll
    for (int nt = 0; nt < 4; nt++) {
        const int cg = bn + wn * 32 + nt * 8 + 2 * (lane & 3);
        const float b0v = bias[cg], b1v = bias[cg + 1];
        *(float2*)(Cout + (size_t)r0 * 128 + cg) = make_float2(acc[nt][0] + b0v, acc[nt][1] + b1v);
        *(float2*)(Cout + (size_t)r1 * 128 + cg) = make_float2(acc[nt][2] + b0v, acc[nt][3] + b1v);
    }
}

// ---------------------------------------------------------------------------
// Attention (round-10 exact: fp32 ex2, scalar masks, FADD row sums)
// ---------------------------------------------------------------------------
struct SmemAttn {
    __half KV[NH * RS2];
    __half Qs[10][16][24];
    int    rowmap[NH];
    unsigned short vmask[NH];
};

__global__ __launch_bounds__(320) void attn_mma(void)
{
    extern __shared__ char smraw[];
    SmemAttn* sm = (SmemAttn*)smraw;

    const int tid  = threadIdx.x;
    const int warp = tid >> 5;
    const int lane = tid & 31;

    const int hp   = blockIdx.x & 3;
    const int tile = blockIdx.x >> 2;
    const int tw   = tile % 6;
    const int th   = tile / 6;
    const int hy0  = th * 2;
    const int wx0  = tw * 8;

    const int hl   = warp / 5;
    const int dt   = warp % 5;
    const int head = hp * 2 + hl;

#pragma unroll
    for (int t = 0; t < 2; t++) {
        int rr = tid + t * 320;
        if (rr < NH) {
            int map = -1;
            unsigned vm = 0;
            if (rr < NREAL) {
                int d   = rr / 112;
                int rem = rr % 112;
                int ih  = rem / 14;
                int iw  = rem % 14;
                int h2  = (hy0 + ih + 21) % HH;
                int w2  = (wx0 + iw + 45) % WWID;
                map = (d * HH + h2) * WWID + w2;
                int wlo = iw - 6 < 0 ? 0 : iw - 6;
                int whi = iw < 7 ? iw : 7;
                unsigned wm = (whi >= wlo) ? ((0xFFu << wlo) & (0xFFu >> (7 - whi))) : 0u;
                unsigned m0 = (ih <= 6) ? wm : 0u;
                unsigned m1 = (ih >= 1) ? wm : 0u;
                vm = m0 | (m1 << 8);
            }
            sm->rowmap[rr] = map;
            sm->vmask[rr]  = (unsigned short)vm;
        }
    }
    {
        int r = lane >> 1, hf = lane & 1;
        int gp = ((dt * HH + hy0 + (r >> 3)) * WWID + wx0 + (r & 7));
        *(uint4*)&sm->Qs[warp][r][hf * 8] =
            *(const uint4*)(g_qh + (size_t)gp * DIMC + head * HD + hf * 8);
    }
    __syncthreads();

#pragma unroll
    for (int t = 0; t < 15; t++) {
        int e = tid + t * 320;
        if (e < NH * 8) {
            int row = e >> 3, c = e & 7;
            int cc  = c & 3;
            int g   = sm->rowmap[row];
            uint4 v = make_uint4(0u, 0u, 0u, 0u);
            const __half* base = (c < 4) ? g_kh : g_vh;
            if (g >= 0) v = *(const uint4*)(base + (size_t)g * DIMC + hp * 32 + cc * 8);
            *(uint4*)&sm->KV[row * RS2 + ((c < 4) ? 0 : 32) + cc * 8] = v;
        }
    }
    __syncthreads();

    const u32 qb  = smaddr(&sm->Qs[warp][0][0]);
    const u32 kvb = smaddr(sm->KV);
    const int r0  = lane >> 2;

    u32 qa0, qa1, qa2, qa3;
    {
        int l4 = lane & 15, cg = lane >> 4;
        ldsm_x4(qa0, qa1, qa2, qa3, qb + (u32)(l4 * 24 + cg * 8) * 2);
    }

    float dacc[8];
#pragma unroll
    for (int i = 0; i < 8; i++) dacc[i] = 0.f;
    float s0 = 0.f, s1 = 0.f;

#pragma unroll
    for (int ch = 0; ch < 8; ch++) {
        const int c0 = ch * 72;
        float c[9][4];
#pragma unroll
        for (int t = 0; t < 9; t++)
            c[t][0] = c[t][1] = c[t][2] = c[t][3] = -SHIFT2;

#pragma unroll
        for (int t = 0; t < 9; t++) {
            int l4 = lane & 15;
            u32 addr = kvb + (u32)((c0 + t * 8 + (l4 & 7)) * RS2 + hl * 16 + (l4 >> 3) * 8) * 2;
            u32 b0, b1;
            ldsm_x2(b0, b1, addr);
            mma16816(c[t], qa0, qa1, qa2, qa3, b0, b1);
        }

#pragma unroll
        for (int t = 0; t < 9; t++) {
            int cA = c0 + t * 8 + 2 * (lane & 3);
            u32 mm = *(const u32*)&sm->vmask[cA];
            float e0 = ex2(c[t][0]);
            float e1 = ex2(c[t][1]);
            float e2 = ex2(c[t][2]);
            float e3 = ex2(c[t][3]);
            e0 = ((mm >> (r0)) & 1u)      ? e0 : 0.f;
            e1 = ((mm >> (16 + r0)) & 1u) ? e1 : 0.f;
            e2 = ((mm >> (8 + r0)) & 1u)  ? e2 : 0.f;
            e3 = ((mm >> (24 + r0)) & 1u) ? e3 : 0.f;
            s0 += e0 + e1;
            s1 += e2 + e3;
            c[t][0] = e0; c[t][1] = e1; c[t][2] = e2; c[t][3] = e3;
        }

#pragma unroll
        for (int kc = 0; kc < 4; kc++) {
            u32 a0 = packh2(c[2 * kc][0], c[2 * kc][1]);
            u32 a1 = packh2(c[2 * kc][2], c[2 * kc][3]);
            u32 a2 = packh2(c[2 * kc + 1][0], c[2 * kc + 1][1]);
            u32 a3 = packh2(c[2 * kc + 1][2], c[2 * kc + 1][3]);
            int g = lane >> 3, rr2 = lane & 7;
            int row = c0 + kc * 16 + ((g & 1) << 3) + rr2;
            u32 addr = kvb + (u32)(row * RS2 + 32 + hl * 16 + (g >> 1) * 8) * 2;
            u32 b0, b1, b2, b3;
            ldsm_x4_t(b0, b1, b2, b3, addr);
            mma16816(dacc,     a0, a1, a2, a3, b0, b1);
            mma16816(dacc + 4, a0, a1, a2, a3, b2, b3);
        }
        {
            u32 a0 = packh2(c[8][0], c[8][1]);
            u32 a1 = packh2(c[8][2], c[8][3]);
            int l4 = lane & 15;
            int row = c0 + 64 + (l4 & 7);
            u32 addr = kvb + (u32)(row * RS2 + 32 + hl * 16 + (l4 >> 3) * 8) * 2;
            u32 b0, b1;
            ldsm_x2_t(b0, b1, addr);
            mma1688(dacc,     a0, a1, b0);
            mma1688(dacc + 4, a0, a1, b1);
        }
    }

    s0 += __shfl_xor_sync(0xFFFFFFFF, s0, 1);
    s0 += __shfl_xor_sync(0xFFFFFFFF, s0, 2);
    s1 += __shfl_xor_sync(0xFFFFFFFF, s1, 1);
    s1 += __shfl_xor_sync(0xFFFFFFFF, s1, 2);
    const float inv0 = 1.f / s0, inv1 = 1.f / s1;

    const int q4 = lane & 3;
    const int gp0 = ((dt * HH + hy0 + 0) * WWID + wx0 + r0);
    const int gp1 = ((dt * HH + hy0 + 1) * WWID + wx0 + r0);
    float* o0 = g_att + (size_t)gp0 * DIMC + head * HD;
    float* o1 = g_att + (size_t)gp1 * DIMC + head * HD;
    *(float2*)(o0 + 2 * q4)     = make_float2(dacc[0] * inv0, dacc[1] * inv0);
    *(float2*)(o1 + 2 * q4)     = make_float2(dacc[2] * inv1, dacc[3] * inv1);
    *(float2*)(o0 + 8 + 2 * q4) = make_float2(dacc[4] * inv0, dacc[5] * inv0);
    *(float2*)(o1 + 8 + 2 * q4) = make_float2(dacc[6] * inv1, dacc[7] * inv1);
}

// ---------------------------------------------------------------------------
extern "C" void kernel_launch(void* const* d_in, const int* in_sizes, int n_in,
                              void* d_out, int out_size)
{
    const float* x      = (const float*)d_in[0];
    const float* qkv_w  = (const float*)d_in[1];
    const float* qkv_b  = (const float*)d_in[2];
    const float* proj_w = (const float*)d_in[3];
    const float* proj_b = (const float*)d_in[4];
    float* out = (float*)d_out;

    float* att;
    cudaGetSymbolAddress((void**)&att, g_att);

    static int attr_set = 0;
    if (!attr_set) {
        cudaFuncSetAttribute(attn_mma, cudaFuncAttributeMaxDynamicSharedMemorySize,
                             (int)sizeof(SmemAttn));
        cudaFuncSetAttribute(gemm_qkv, cudaFuncAttributeMaxDynamicSharedMemorySize,
                             (int)sizeof(SmemGemm));
        cudaFuncSetAttribute(gemm_proj, cudaFuncAttributeMaxDynamicSharedMemorySize,
                             (int)sizeof(SmemProj));
        attr_set = 1;
    }

    // 0) one-shot hi/lo split of x and weights
    split_prep<<<(200704 + 255) / 256, 256>>>(x, qkv_w, proj_w);
    // 1) QKV projection (presplit fp16 TC GEMM)
    gemm_qkv<<<dim3(NP / 64, 384 / 64), 256, sizeof(SmemGemm)>>>(qkv_b);
    // 2) neighborhood attention (round-10 config)
    attn_mma<<<72 * 4, 320, sizeof(SmemAttn)>>>();
    // 3) output projection (32x64 tiles, 360 blocks)
    gemm_proj<<<dim3(NP / 32, 128 / 64), 128, sizeof(SmemProj)>>>(att, proj_b, out);
}

// round 14
// speedup vs baseline: 1.0480x; 1.0069x over previous
#include <cuda_runtime.h>
#include <cuda_fp16.h>
#include <math.h>

#define DIMC   128
#define HEADS  8
#define HD     16
#define DD     5
#define HH     24
#define WWID   48
#define NP     (DD*HH*WWID)   /* 5760 */
#define NH     576            /* padded halo rows (560 real) */
#define NREAL  560
#define RS2    72             /* attn KV row stride in halves (144B) */
#define GS2    72             /* qkv gemm smem row stride in halves */
#define GS3    136            /* proj gemm smem row stride (K=128 + pad) */

#define LOG2E      1.4426950408889634f
#define SHIFT2     5.7707801635558535f   /* 4*log2e */

typedef unsigned int u32;

// Scratch
__device__ __half g_xh[NP * DIMC],  g_xl[NP * DIMC];
__device__ __half g_wqh[384 * 128], g_wql[384 * 128];
__device__ __half g_wph[128 * 128], g_wpl[128 * 128];
__device__ __half g_qh[NP * DIMC];
__device__ __half g_kh[NP * DIMC];
__device__ __half g_vh[NP * DIMC];
__device__ float  g_att[NP * DIMC];

// ---------------------------------------------------------------------------
// helpers
// ---------------------------------------------------------------------------
__device__ __forceinline__ u32 smaddr(const void* p) { return (u32)__cvta_generic_to_shared(p); }

__device__ __forceinline__ void ldsm_x4(u32& r0, u32& r1, u32& r2, u32& r3, u32 a) {
    asm volatile("ldmatrix.sync.aligned.m8n8.x4.shared.b16 {%0,%1,%2,%3},[%4];"
                 : "=r"(r0), "=r"(r1), "=r"(r2), "=r"(r3) : "r"(a));
}
__device__ __forceinline__ void ldsm_x2(u32& r0, u32& r1, u32 a) {
    asm volatile("ldmatrix.sync.aligned.m8n8.x2.shared.b16 {%0,%1},[%2];"
                 : "=r"(r0), "=r"(r1) : "r"(a));
}
__device__ __forceinline__ void ldsm_x4_t(u32& r0, u32& r1, u32& r2, u32& r3, u32 a) {
    asm volatile("ldmatrix.sync.aligned.m8n8.x4.trans.shared.b16 {%0,%1,%2,%3},[%4];"
                 : "=r"(r0), "=r"(r1), "=r"(r2), "=r"(r3) : "r"(a));
}
__device__ __forceinline__ void ldsm_x2_t(u32& r0, u32& r1, u32 a) {
    asm volatile("ldmatrix.sync.aligned.m8n8.x2.trans.shared.b16 {%0,%1},[%2];"
                 : "=r"(r0), "=r"(r1) : "r"(a));
}
__device__ __forceinline__ void mma16816(float* d, u32 a0, u32 a1, u32 a2, u32 a3, u32 b0, u32 b1) {
    asm volatile("mma.sync.aligned.m16n8k16.row.col.f32.f16.f16.f32 "
                 "{%0,%1,%2,%3},{%4,%5,%6,%7},{%8,%9},{%0,%1,%2,%3};"
                 : "+f"(d[0]), "+f"(d[1]), "+f"(d[2]), "+f"(d[3])
                 : "r"(a0), "r"(a1), "r"(a2), "r"(a3), "r"(b0), "r"(b1));
}
__device__ __forceinline__ void mma1688(float* d, u32 a0, u32 a1, u32 b0) {
    asm volatile("mma.sync.aligned.m16n8k8.row.col.f32.f16.f16.f32 "
                 "{%0,%1,%2,%3},{%4,%5},{%6},{%0,%1,%2,%3};"
                 : "+f"(d[0]), "+f"(d[1]), "+f"(d[2]), "+f"(d[3])
                 : "r"(a0), "r"(a1), "r"(b0));
}
__device__ __forceinline__ u32 packh2(float x, float y) {
    __half2 h = __floats2half2_rn(x, y);
    return *(u32*)&h;
}
__device__ __forceinline__ u32 ex2h2(u32 x) {
    u32 r;
    asm("ex2.approx.f16x2 %0, %1;" : "=r"(r) : "r"(x));
    return r;
}
__device__ __forceinline__ u32 hadd2(u32 a, u32 b) {
    u32 r;
    asm("add.f16x2 %0, %1, %2;" : "=r"(r) : "r"(a), "r"(b));
    return r;
}
__device__ __forceinline__ float h2sumf(u32 h) {
    __half2 v = *(__half2*)&h;
    return __low2float(v) + __high2float(v);
}
__device__ __forceinline__ void split2(float x, float y, u32& hi, u32& lo) {
    __half hx = __float2half_rn(x), hy = __float2half_rn(y);
    __half2 h2 = __halves2half2(hx, hy);
    hi = *(u32*)&h2;
    __half2 l2 = __floats2half2_rn(x - __half2float(hx), y - __half2float(hy));
    lo = *(u32*)&l2;
}

// ---------------------------------------------------------------------------
// Prep: split x / qkv_w / proj_w into hi/lo fp16, once.
// ---------------------------------------------------------------------------
__global__ __launch_bounds__(256) void split_prep(const float* __restrict__ x,
                                                  const float* __restrict__ wq,
                                                  const float* __restrict__ wp)
{
    int i = blockIdx.x * 256 + threadIdx.x;
    const float* src;
    __half *dh, *dl;
    int off;
    if (i < 184320)      { src = x;  dh = g_xh;  dl = g_xl;  off = i; }
    else if (i < 196608) { src = wq; dh = g_wqh; dl = g_wql; off = i - 184320; }
    else if (i < 200704) { src = wp; dh = g_wph; dl = g_wpl; off = i - 196608; }
    else return;
    float4 v = ((const float4*)src)[off];
    u32 h0, l0, h1, l1;
    split2(v.x, v.y, h0, l0);
    split2(v.z, v.w, h1, l1);
    *(uint2*)(dh + off * 4) = make_uint2(h0, h1);
    *(uint2*)(dl + off * 4) = make_uint2(l0, l1);
}

// ---------------------------------------------------------------------------
// QKV GEMM (round-10): presplit operands, 64x64, K in 2 chunks
// ---------------------------------------------------------------------------
struct SmemGemm {
    __half Ah[64 * GS2];
    __half Al[64 * GS2];
    __half Bh[64 * GS2];
    __half Bl[64 * GS2];
};

__global__ __launch_bounds__(256, 4) void gemm_qkv(const float* __restrict__ bias)
{
    extern __shared__ char smraw[];
    SmemGemm* sm = (SmemGemm*)smraw;
    const int tid = threadIdx.x, warp = tid >> 5, lane = tid & 31;
    const int bm = blockIdx.x * 64, bn = blockIdx.y * 64;

    const int wm = warp >> 1, wn = warp & 1;
    const u32 aoff  = (u32)((wm * 16 + (lane & 15)) * GS2 + (lane >> 4) * 8) * 2;
    const u32 boff0 = (u32)((wn * 32 +      (lane & 15)) * GS2 + (lane >> 4) * 8) * 2;
    const u32 boff1 = (u32)((wn * 32 + 16 + (lane & 15)) * GS2 + (lane >> 4) * 8) * 2;
    const u32 ah_b  = smaddr(sm->Ah) + aoff;
    const u32 al_b  = smaddr(sm->Al) + aoff;
    const u32 bh_b0 = smaddr(sm->Bh) + boff0, bh_b1 = smaddr(sm->Bh) + boff1;
    const u32 bl_b0 = smaddr(sm->Bl) + boff0, bl_b1 = smaddr(sm->Bl) + boff1;

    float acc[4][4] = {};

    for (int k0 = 0; k0 < 128; k0 += 64) {
        if (k0) __syncthreads();
#pragma unroll
        for (int t = 0; t < 2; t++) {
            int e = tid + t * 256;
            int row = e >> 3, c = e & 7;
            int gcol = k0 + c * 8;
            *(uint4*)(sm->Ah + row * GS2 + c * 8) = *(const uint4*)(g_xh  + (size_t)(bm + row) * 128 + gcol);
            *(uint4*)(sm->Al + row * GS2 + c * 8) = *(const uint4*)(g_xl  + (size_t)(bm + row) * 128 + gcol);
            *(uint4*)(sm->Bh + row * GS2 + c * 8) = *(const uint4*)(g_wqh + (size_t)(bn + row) * 128 + gcol);
            *(uint4*)(sm->Bl + row * GS2 + c * 8) = *(const uint4*)(g_wql + (size_t)(bn + row) * 128 + gcol);
        }
        __syncthreads();

#pragma unroll
        for (int ks = 0; ks < 4; ks++) {
            const u32 kb = ks * 32;
            u32 ah0, ah1, ah2, ah3;
            u32 b0, b1, b2, b3, b4, b5, b6, b7;
            ldsm_x4(ah0, ah1, ah2, ah3, ah_b + kb);
            ldsm_x4(b0, b1, b2, b3, bh_b0 + kb);
            ldsm_x4(b4, b5, b6, b7, bh_b1 + kb);
            mma16816(acc[0], ah0, ah1, ah2, ah3, b0, b2);
            mma16816(acc[1], ah0, ah1, ah2, ah3, b1, b3);
            mma16816(acc[2], ah0, ah1, ah2, ah3, b4, b6);
            mma16816(acc[3], ah0, ah1, ah2, ah3, b5, b7);
            {
                u32 al0, al1, al2, al3;
                ldsm_x4(al0, al1, al2, al3, al_b + kb);
                mma16816(acc[0], al0, al1, al2, al3, b0, b2);
                mma16816(acc[1], al0, al1, al2, al3, b1, b3);
                mma16816(acc[2], al0, al1, al2, al3, b4, b6);
                mma16816(acc[3], al0, al1, al2, al3, b5, b7);
            }
            ldsm_x4(b0, b1, b2, b3, bl_b0 + kb);
            ldsm_x4(b4, b5, b6, b7, bl_b1 + kb);
            mma16816(acc[0], ah0, ah1, ah2, ah3, b0, b2);
            mma16816(acc[1], ah0, ah1, ah2, ah3, b1, b3);
            mma16816(acc[2], ah0, ah1, ah2, ah3, b4, b6);
            mma16816(acc[3], ah0, ah1, ah2, ah3, b5, b7);
        }
    }

    const int r0 = bm + wm * 16 + (lane >> 2);
    const int r1 = r0 + 8;
#pragma unroll
    for (int nt = 0; nt < 4; nt++) {
        const int cg = bn + wn * 32 + nt * 8 + 2 * (lane & 3);
        const float b0v = bias[cg], b1v = bias[cg + 1];
        float v00 = acc[nt][0] + b0v, v01 = acc[nt][1] + b1v;
        float v10 = acc[nt][2] + b0v, v11 = acc[nt][3] + b1v;
        const int seg = cg >> 7;
        const int lc  = cg - seg * 128;
        __half* base = (seg == 0) ? g_qh : (seg == 1) ? g_kh : g_vh;
        if (seg == 0) {
            const float qs = 0.25f * LOG2E;
            v00 *= qs; v01 *= qs; v10 *= qs; v11 *= qs;
        }
        *(__half2*)(base + (size_t)r0 * DIMC + lc) = __floats2half2_rn(v00, v01);
        *(__half2*)(base + (size_t)r1 * DIMC + lc) = __floats2half2_rn(v10, v11);
    }
}

// ---------------------------------------------------------------------------
// Proj GEMM v2 (measured 9.9us): 32x64 tile, 128 threads, K=128 single pass.
// ---------------------------------------------------------------------------
struct SmemProj {
    __half Ah[32 * GS3];
    __half Al[32 * GS3];
    __half Bh[64 * GS3];
    __half Bl[64 * GS3];
};

__global__ __launch_bounds__(128, 4) void gemm_proj(const float* __restrict__ A,
                                                    const float* __restrict__ bias,
                                                    float* __restrict__ Cout)
{
    extern __shared__ char smraw[];
    SmemProj* sm = (SmemProj*)smraw;
    const int tid = threadIdx.x, warp = tid >> 5, lane = tid & 31;
    const int bm = blockIdx.x * 32, bn = blockIdx.y * 64;

    {
        const int row = tid >> 2, q = tid & 3;
        const float* Ar = A + (size_t)(bm + row) * 128 + q * 32;
        __half* ah = sm->Ah + row * GS3 + q * 32;
        __half* al = sm->Al + row * GS3 + q * 32;
#pragma unroll
        for (int j = 0; j < 8; j++) {
            float4 v = *(const float4*)(Ar + j * 4);
            u32 h0, l0, h1, l1;
            split2(v.x, v.y, h0, l0);
            split2(v.z, v.w, h1, l1);
            *(uint2*)(ah + j * 4) = make_uint2(h0, h1);
            *(uint2*)(al + j * 4) = make_uint2(l0, l1);
        }
#pragma unroll
        for (int t = 0; t < 8; t++) {
            int e = tid + t * 128;
            int rowb = e >> 4, c = e & 15;
            *(uint4*)(sm->Bh + rowb * GS3 + c * 8) = *(const uint4*)(g_wph + (size_t)(bn + rowb) * 128 + c * 8);
            *(uint4*)(sm->Bl + rowb * GS3 + c * 8) = *(const uint4*)(g_wpl + (size_t)(bn + rowb) * 128 + c * 8);
        }
    }
    __syncthreads();

    const int wm = warp >> 1, wn = warp & 1;
    const u32 aoff  = (u32)((wm * 16 + (lane & 15)) * GS3 + (lane >> 4) * 8) * 2;
    const u32 boff0 = (u32)((wn * 32 +      (lane & 15)) * GS3 + (lane >> 4) * 8) * 2;
    const u32 boff1 = (u32)((wn * 32 + 16 + (lane & 15)) * GS3 + (lane >> 4) * 8) * 2;
    const u32 ah_b  = smaddr(sm->Ah) + aoff;
    const u32 al_b  = smaddr(sm->Al) + aoff;
    const u32 bh_b0 = smaddr(sm->Bh) + boff0, bh_b1 = smaddr(sm->Bh) + boff1;
    const u32 bl_b0 = smaddr(sm->Bl) + boff0, bl_b1 = smaddr(sm->Bl) + boff1;

    float acc[4][4] = {};
#pragma unroll
    for (int ks = 0; ks < 8; ks++) {
        const u32 kb = ks * 32;
        u32 ah0, ah1, ah2, ah3;
        u32 b0, b1, b2, b3, b4, b5, b6, b7;
        ldsm_x4(ah0, ah1, ah2, ah3, ah_b + kb);
        ldsm_x4(b0, b1, b2, b3, bh_b0 + kb);
        ldsm_x4(b4, b5, b6, b7, bh_b1 + kb);
        mma16816(acc[0], ah0, ah1, ah2, ah3, b0, b2);
        mma16816(acc[1], ah0, ah1, ah2, ah3, b1, b3);
        mma16816(acc[2], ah0, ah1, ah2, ah3, b4, b6);
        mma16816(acc[3], ah0, ah1, ah2, ah3, b5, b7);
        {
            u32 al0, al1, al2, al3;
            ldsm_x4(al0, al1, al2, al3, al_b + kb);
            mma16816(acc[0], al0, al1, al2, al3, b0, b2);
            mma16816(acc[1], al0, al1, al2, al3, b1, b3);
            mma16816(acc[2], al0, al1, al2, al3, b4, b6);
            mma16816(acc[3], al0, al1, al2, al3, b5, b7);
        }
        ldsm_x4(b0, b1, b2, b3, bl_b0 + kb);
        ldsm_x4(b4, b5, b6, b7, bl_b1 + kb);
        mma16816(acc[0], ah0, ah1, ah2, ah3, b0, b2);
        mma16816(acc[1], ah0, ah1, ah2, ah3, b1, b3);
        mma16816(acc[2], ah0, ah1, ah2, ah3, b4, b6);
        mma16816(acc[3], ah0, ah1, ah2, ah3, b5, b7);
    }

    const int r0 = bm + wm * 16 + (lane >> 2);
    const int r1 = r0 + 8;
#pragma unroll
    for (int nt = 0; nt < 4; nt++) {
        const int cg = bn + wn * 32 + nt * 8 + 2 * (lane & 3);
        const float b0v = bias[cg], b1v = bias[cg + 1];
        *(float2*)(Cout + (size_t)r0 * 128 + cg) = make_float2(acc[nt][0] + b0v, acc[nt][1] + b1v);
        *(float2*)(Cout + (size_t)r1 * 128 + cg) = make_float2(acc[nt][2] + b0v, acc[nt][3] + b1v);
    }
}

// ---------------------------------------------------------------------------
// Attention v5: fp16x2 exp on PV-ready packed pairs, precomputed AND-masks,
// fp16x2 partial row sums with per-chunk fp32 flush. No extra mma vs r10.
// ---------------------------------------------------------------------------
struct SmemAttn {
    __half KV[NH * RS2];         // 82944 B
    __half Qs[10][16][24];       // 7680 B
    int    rowmap[NH];           // 2304 B
    uint2  pmask[288 * 8];       // 18432 B  [pair][r0] -> (mask row0, mask row1)
};                                // total 111360 B -> 2 CTAs/SM (217.5KB <= 228KB)

__global__ __launch_bounds__(320) void attn_mma(void)
{
    extern __shared__ char smraw[];
    SmemAttn* sm = (SmemAttn*)smraw;

    const int tid  = threadIdx.x;
    const int warp = tid >> 5;
    const int lane = tid & 31;

    const int hp   = blockIdx.x & 3;
    const int tile = blockIdx.x >> 2;
    const int tw   = tile % 6;
    const int th   = tile / 6;
    const int hy0  = th * 2;
    const int wx0  = tw * 8;

    const int hl   = warp / 5;
    const int dt   = warp % 5;
    const int head = hp * 2 + hl;

    // ---- phase A: rowmap + pmask + per-warp Q tile ----
#pragma unroll
    for (int t = 0; t < 2; t++) {
        int rr = tid + t * 320;
        if (rr < NH) {
            int map = -1;
            if (rr < NREAL) {
                int d   = rr / 112;
                int rem = rr % 112;
                int ih  = rem / 14;
                int iw  = rem % 14;
                int h2  = (hy0 + ih + 21) % HH;
                int w2  = (wx0 + iw + 45) % WWID;
                map = (d * HH + h2) * WWID + w2;
            }
            sm->rowmap[rr] = map;
        }
    }
    for (int idx = tid; idx < 288 * 8; idx += 320) {
        int pi = idx >> 3, jr = idx & 7;
        u32 m0 = 0, m1 = 0;
#pragma unroll
        for (int s = 0; s < 2; s++) {
            int cc = pi * 2 + s;
            if (cc < NREAL) {
                int rem = cc % 112;
                int ih = rem / 14, iw = rem % 14;
                bool wv = (iw >= jr) && (iw <= jr + 6);
                u32 half = s ? 0xFFFF0000u : 0x0000FFFFu;
                if (wv && ih <= 6) m0 |= half;
                if (wv && ih >= 1) m1 |= half;
            }
        }
        sm->pmask[idx] = make_uint2(m0, m1);
    }
    {
        int r = lane >> 1, hf = lane & 1;
        int gp = ((dt * HH + hy0 + (r >> 3)) * WWID + wx0 + (r & 7));
        *(uint4*)&sm->Qs[warp][r][hf * 8] =
            *(const uint4*)(g_qh + (size_t)gp * DIMC + head * HD + hf * 8);
    }
    __syncthreads();

    // ---- phase B: KV gather (both heads of the pair), 16B vectorized ----
#pragma unroll
    for (int t = 0; t < 15; t++) {
        int e = tid + t * 320;
        if (e < NH * 8) {
            int row = e >> 3, c = e & 7;
            int cc  = c & 3;
            int g   = sm->rowmap[row];
            uint4 v = make_uint4(0u, 0u, 0u, 0u);
            const __half* base = (c < 4) ? g_kh : g_vh;
            if (g >= 0) v = *(const uint4*)(base + (size_t)g * DIMC + hp * 32 + cc * 8);
            *(uint4*)&sm->KV[row * RS2 + ((c < 4) ? 0 : 32) + cc * 8] = v;
        }
    }
    __syncthreads();

    // ---- compute: fully warp-local ----
    const u32 qb  = smaddr(&sm->Qs[warp][0][0]);
    const u32 kvb = smaddr(sm->KV);
    const int r0  = lane >> 2;
    const int q4  = lane & 3;

    u32 qa0, qa1, qa2, qa3;
    {
        int l4 = lane & 15, cg = lane >> 4;
        ldsm_x4(qa0, qa1, qa2, qa3, qb + (u32)(l4 * 24 + cg * 8) * 2);
    }

    float dacc[8];
#pragma unroll
    for (int i = 0; i < 8; i++) dacc[i] = 0.f;
    float s0 = 0.f, s1 = 0.f;

#pragma unroll
    for (int ch = 0; ch < 8; ch++) {
        const int c0 = ch * 72;
        float c[9][4];
#pragma unroll
        for (int t = 0; t < 9; t++)
            c[t][0] = c[t][1] = c[t][2] = c[t][3] = -SHIFT2;

        // QK scores (log2 domain, shift pre-loaded)
#pragma unroll
        for (int t = 0; t < 9; t++) {
            int l4 = lane & 15;
            u32 addr = kvb + (u32)((c0 + t * 8 + (l4 & 7)) * RS2 + hl * 16 + (l4 >> 3) * 8) * 2;
            u32 b0, b1;
            ldsm_x2(b0, b1, addr);
            mma16816(c[t], qa0, qa1, qa2, qa3, b0, b1);
        }

        // pack -> fp16x2 exp -> precomputed AND-mask; accumulate sums in f16x2
        u32 af0[9], af1[9];
        u32 hs0 = 0u, hs1 = 0u;
#pragma unroll
        for (int t = 0; t < 9; t++) {
            int pi = (ch * 36) + t * 4 + q4;          // (c0 + t*8 + 2*q4)/2
            uint2 mm = sm->pmask[pi * 8 + r0];
            u32 e0 = ex2h2(packh2(c[t][0], c[t][1])) & mm.x;
            u32 e1 = ex2h2(packh2(c[t][2], c[t][3])) & mm.y;
            af0[t] = e0;
            af1[t] = e1;
            hs0 = hadd2(hs0, e0);
            hs1 = hadd2(hs1, e1);
        }
        s0 += h2sumf(hs0);
        s1 += h2sumf(hs1);

        // PV accumulate — A fragments are the packed exp values directly
#pragma unroll
        for (int kc = 0; kc < 4; kc++) {
            u32 a0 = af0[2 * kc],     a1 = af1[2 * kc];
            u32 a2 = af0[2 * kc + 1], a3 = af1[2 * kc + 1];
            int g = lane >> 3, rr2 = lane & 7;
            int row = c0 + kc * 16 + ((g & 1) << 3) + rr2;
            u32 addr = kvb + (u32)(row * RS2 + 32 + hl * 16 + (g >> 1) * 8) * 2;
            u32 b0, b1, b2, b3;
            ldsm_x4_t(b0, b1, b2, b3, addr);
            mma16816(dacc,     a0, a1, a2, a3, b0, b1);
            mma16816(dacc + 4, a0, a1, a2, a3, b2, b3);
        }
        {   // tail cols c0+64..71
            int l4 = lane & 15;
            int row = c0 + 64 + (l4 & 7);
            u32 addr = kvb + (u32)(row * RS2 + 32 + hl * 16 + (l4 >> 3) * 8) * 2;
            u32 b0, b1;
            ldsm_x2_t(b0, b1, addr);
            mma1688(dacc,     af0[8], af1[8], b0);
            mma1688(dacc + 4, af0[8], af1[8], b1);
        }
    }

    s0 += __shfl_xor_sync(0xFFFFFFFF, s0, 1);
    s0 += __shfl_xor_sync(0xFFFFFFFF, s0, 2);
    s1 += __shfl_xor_sync(0xFFFFFFFF, s1, 1);
    s1 += __shfl_xor_sync(0xFFFFFFFF, s1, 2);
    const float inv0 = 1.f / s0, inv1 = 1.f / s1;

    const int gp0 = ((dt * HH + hy0 + 0) * WWID + wx0 + r0);
    const int gp1 = ((dt * HH + hy0 + 1) * WWID + wx0 + r0);
    float* o0 = g_att + (size_t)gp0 * DIMC + head * HD;
    float* o1 = g_att + (size_t)gp1 * DIMC + head * HD;
    *(float2*)(o0 + 2 * q4)     = make_float2(dacc[0] * inv0, dacc[1] * inv0);
    *(float2*)(o1 + 2 * q4)     = make_float2(dacc[2] * inv1, dacc[3] * inv1);
    *(float2*)(o0 + 8 + 2 * q4) = make_float2(dacc[4] * inv0, dacc[5] * inv0);
    *(float2*)(o1 + 8 + 2 * q4) = make_float2(dacc[6] * inv1, dacc[7] * inv1);
}

// ---------------------------------------------------------------------------
extern "C" void kernel_launch(void* const* d_in, const int* in_sizes, int n_in,
                              void* d_out, int out_size)
{
    const float* x      = (const float*)d_in[0];
    const float* qkv_w  = (const float*)d_in[1];
    const float* qkv_b  = (const float*)d_in[2];
    const float* proj_w = (const float*)d_in[3];
    const float* proj_b = (const float*)d_in[4];
    float* out = (float*)d_out;

    float* att;
    cudaGetSymbolAddress((void**)&att, g_att);

    static int attr_set = 0;
    if (!attr_set) {
        cudaFuncSetAttribute(attn_mma, cudaFuncAttributeMaxDynamicSharedMemorySize,
                             (int)sizeof(SmemAttn));
        cudaFuncSetAttribute(gemm_qkv, cudaFuncAttributeMaxDynamicSharedMemorySize,
                             (int)sizeof(SmemGemm));
        cudaFuncSetAttribute(gemm_proj, cudaFuncAttributeMaxDynamicSharedMemorySize,
                             (int)sizeof(SmemProj));
        attr_set = 1;
    }

    // 0) one-shot hi/lo split of x and weights
    split_prep<<<(200704 + 255) / 256, 256>>>(x, qkv_w, proj_w);
    // 1) QKV projection (presplit fp16 TC GEMM)
    gemm_qkv<<<dim3(NP / 64, 384 / 64), 256, sizeof(SmemGemm)>>>(qkv_b);
    // 2) neighborhood attention v5 (fp16x2 exp, AND-masks, no extra mma)
    attn_mma<<<72 * 4, 320, sizeof(SmemAttn)>>>();
    // 3) output projection (32x64 tiles, 360 blocks)
    gemm_proj<<<dim3(NP / 32, 128 / 64), 128, sizeof(SmemProj)>>>(att, proj_b, out);
}

// round 16
// speedup vs baseline: 1.1088x; 1.0580x over previous
#include <cuda_runtime.h>
#include <cuda_fp16.h>
#include <math.h>

#define DIMC   128
#define HEADS  8
#define HD     16
#define DD     5
#define HH     24
#define WWID   48
#define NP     (DD*HH*WWID)   /* 5760 */
#define NH     576            /* padded halo rows (560 real) */
#define NREAL  560
#define RS2    72             /* attn KV row stride in halves (144B) */
#define GS2    72             /* qkv gemm smem row stride in halves */
#define GS3    136            /* proj gemm smem row stride (K=128 + pad) */

#define LOG2E      1.4426950408889634f
#define SHIFT2     5.7707801635558535f   /* 4*log2e */

typedef unsigned int u32;

// Scratch
__device__ __half g_xh[NP * DIMC],  g_xl[NP * DIMC];
__device__ __half g_wqh[384 * 128], g_wql[384 * 128];
__device__ __half g_wph[128 * 128], g_wpl[128 * 128];
__device__ __half g_qh[NP * DIMC];
__device__ __half g_kh[NP * DIMC];
__device__ __half g_vh[NP * DIMC];
__device__ float  g_att[NP * DIMC];

// ---------------------------------------------------------------------------
// helpers
// ---------------------------------------------------------------------------
__device__ __forceinline__ u32 smaddr(const void* p) { return (u32)__cvta_generic_to_shared(p); }

__device__ __forceinline__ void ldsm_x4(u32& r0, u32& r1, u32& r2, u32& r3, u32 a) {
    asm volatile("ldmatrix.sync.aligned.m8n8.x4.shared.b16 {%0,%1,%2,%3},[%4];"
                 : "=r"(r0), "=r"(r1), "=r"(r2), "=r"(r3) : "r"(a));
}
__device__ __forceinline__ void ldsm_x2(u32& r0, u32& r1, u32 a) {
    asm volatile("ldmatrix.sync.aligned.m8n8.x2.shared.b16 {%0,%1},[%2];"
                 : "=r"(r0), "=r"(r1) : "r"(a));
}
__device__ __forceinline__ void ldsm_x4_t(u32& r0, u32& r1, u32& r2, u32& r3, u32 a) {
    asm volatile("ldmatrix.sync.aligned.m8n8.x4.trans.shared.b16 {%0,%1,%2,%3},[%4];"
                 : "=r"(r0), "=r"(r1), "=r"(r2), "=r"(r3) : "r"(a));
}
__device__ __forceinline__ void ldsm_x2_t(u32& r0, u32& r1, u32 a) {
    asm volatile("ldmatrix.sync.aligned.m8n8.x2.trans.shared.b16 {%0,%1},[%2];"
                 : "=r"(r0), "=r"(r1) : "r"(a));
}
__device__ __forceinline__ void mma16816(float* d, u32 a0, u32 a1, u32 a2, u32 a3, u32 b0, u32 b1) {
    asm volatile("mma.sync.aligned.m16n8k16.row.col.f32.f16.f16.f32 "
                 "{%0,%1,%2,%3},{%4,%5,%6,%7},{%8,%9},{%0,%1,%2,%3};"
                 : "+f"(d[0]), "+f"(d[1]), "+f"(d[2]), "+f"(d[3])
                 : "r"(a0), "r"(a1), "r"(a2), "r"(a3), "r"(b0), "r"(b1));
}
__device__ __forceinline__ void mma1688(float* d, u32 a0, u32 a1, u32 b0) {
    asm volatile("mma.sync.aligned.m16n8k8.row.col.f32.f16.f16.f32 "
                 "{%0,%1,%2,%3},{%4,%5},{%6},{%0,%1,%2,%3};"
                 : "+f"(d[0]), "+f"(d[1]), "+f"(d[2]), "+f"(d[3])
                 : "r"(a0), "r"(a1), "r"(b0));
}
__device__ __forceinline__ u32 packh2(float x, float y) {
    __half2 h = __floats2half2_rn(x, y);
    return *(u32*)&h;
}
__device__ __forceinline__ float ex2(float x) {
    float r;
    asm("ex2.approx.f32 %0, %1;" : "=f"(r) : "f"(x));
    return r;
}
__device__ __forceinline__ void cpasync16(u32 dst, const void* src) {
    asm volatile("cp.async.cg.shared.global [%0], [%1], 16;" :: "r"(dst), "l"(src));
}
__device__ __forceinline__ void cpasync_commit() {
    asm volatile("cp.async.commit_group;" ::: "memory");
}
template<int N>
__device__ __forceinline__ void cpasync_wait() {
    asm volatile("cp.async.wait_group %0;" :: "n"(N) : "memory");
}
__device__ __forceinline__ void split2(float x, float y, u32& hi, u32& lo) {
    __half hx = __float2half_rn(x), hy = __float2half_rn(y);
    __half2 h2 = __halves2half2(hx, hy);
    hi = *(u32*)&h2;
    __half2 l2 = __floats2half2_rn(x - __half2float(hx), y - __half2float(hy));
    lo = *(u32*)&l2;
}

// ---------------------------------------------------------------------------
// Prep: split x / qkv_w / proj_w into hi/lo fp16, once.
// ---------------------------------------------------------------------------
__global__ __launch_bounds__(256) void split_prep(const float* __restrict__ x,
                                                  const float* __restrict__ wq,
                                                  const float* __restrict__ wp)
{
    int i = blockIdx.x * 256 + threadIdx.x;
    const float* src;
    __half *dh, *dl;
    int off;
    if (i < 184320)      { src = x;  dh = g_xh;  dl = g_xl;  off = i; }
    else if (i < 196608) { src = wq; dh = g_wqh; dl = g_wql; off = i - 184320; }
    else if (i < 200704) { src = wp; dh = g_wph; dl = g_wpl; off = i - 196608; }
    else return;
    float4 v = ((const float4*)src)[off];
    u32 h0, l0, h1, l1;
    split2(v.x, v.y, h0, l0);
    split2(v.z, v.w, h1, l1);
    *(uint2*)(dh + off * 4) = make_uint2(h0, h1);
    *(uint2*)(dl + off * 4) = make_uint2(l0, l1);
}

// ---------------------------------------------------------------------------
// QKV GEMM (round-10): presplit operands, 64x64, K in 2 chunks
// ---------------------------------------------------------------------------
struct SmemGemm {
    __half Ah[64 * GS2];
    __half Al[64 * GS2];
    __half Bh[64 * GS2];
    __half Bl[64 * GS2];
};

__global__ __launch_bounds__(256, 4) void gemm_qkv(const float* __restrict__ bias)
{
    extern __shared__ char smraw[];
    SmemGemm* sm = (SmemGemm*)smraw;
    const int tid = threadIdx.x, warp = tid >> 5, lane = tid & 31;
    const int bm = blockIdx.x * 64, bn = blockIdx.y * 64;

    const int wm = warp >> 1, wn = warp & 1;
    const u32 aoff  = (u32)((wm * 16 + (lane & 15)) * GS2 + (lane >> 4) * 8) * 2;
    const u32 boff0 = (u32)((wn * 32 +      (lane & 15)) * GS2 + (lane >> 4) * 8) * 2;
    const u32 boff1 = (u32)((wn * 32 + 16 + (lane & 15)) * GS2 + (lane >> 4) * 8) * 2;
    const u32 ah_b  = smaddr(sm->Ah) + aoff;
    const u32 al_b  = smaddr(sm->Al) + aoff;
    const u32 bh_b0 = smaddr(sm->Bh) + boff0, bh_b1 = smaddr(sm->Bh) + boff1;
    const u32 bl_b0 = smaddr(sm->Bl) + boff0, bl_b1 = smaddr(sm->Bl) + boff1;

    float acc[4][4] = {};

    for (int k0 = 0; k0 < 128; k0 += 64) {
        if (k0) __syncthreads();
#pragma unroll
        for (int t = 0; t < 2; t++) {
            int e = tid + t * 256;
            int row = e >> 3, c = e & 7;
            int gcol = k0 + c * 8;
            *(uint4*)(sm->Ah + row * GS2 + c * 8) = *(const uint4*)(g_xh  + (size_t)(bm + row) * 128 + gcol);
            *(uint4*)(sm->Al + row * GS2 + c * 8) = *(const uint4*)(g_xl  + (size_t)(bm + row) * 128 + gcol);
            *(uint4*)(sm->Bh + row * GS2 + c * 8) = *(const uint4*)(g_wqh + (size_t)(bn + row) * 128 + gcol);
            *(uint4*)(sm->Bl + row * GS2 + c * 8) = *(const uint4*)(g_wql + (size_t)(bn + row) * 128 + gcol);
        }
        __syncthreads();

#pragma unroll
        for (int ks = 0; ks < 4; ks++) {
            const u32 kb = ks * 32;
            u32 ah0, ah1, ah2, ah3;
            u32 b0, b1, b2, b3, b4, b5, b6, b7;
            ldsm_x4(ah0, ah1, ah2, ah3, ah_b + kb);
            ldsm_x4(b0, b1, b2, b3, bh_b0 + kb);
            ldsm_x4(b4, b5, b6, b7, bh_b1 + kb);
            mma16816(acc[0], ah0, ah1, ah2, ah3, b0, b2);
            mma16816(acc[1], ah0, ah1, ah2, ah3, b1, b3);
            mma16816(acc[2], ah0, ah1, ah2, ah3, b4, b6);
            mma16816(acc[3], ah0, ah1, ah2, ah3, b5, b7);
            {
                u32 al0, al1, al2, al3;
                ldsm_x4(al0, al1, al2, al3, al_b + kb);
                mma16816(acc[0], al0, al1, al2, al3, b0, b2);
                mma16816(acc[1], al0, al1, al2, al3, b1, b3);
                mma16816(acc[2], al0, al1, al2, al3, b4, b6);
                mma16816(acc[3], al0, al1, al2, al3, b5, b7);
            }
            ldsm_x4(b0, b1, b2, b3, bl_b0 + kb);
            ldsm_x4(b4, b5, b6, b7, bl_b1 + kb);
            mma16816(acc[0], ah0, ah1, ah2, ah3, b0, b2);
            mma16816(acc[1], ah0, ah1, ah2, ah3, b1, b3);
            mma16816(acc[2], ah0, ah1, ah2, ah3, b4, b6);
            mma16816(acc[3], ah0, ah1, ah2, ah3, b5, b7);
        }
    }

    const int r0 = bm + wm * 16 + (lane >> 2);
    const int r1 = r0 + 8;
#pragma unroll
    for (int nt = 0; nt < 4; nt++) {
        const int cg = bn + wn * 32 + nt * 8 + 2 * (lane & 3);
        const float b0v = bias[cg], b1v = bias[cg + 1];
        float v00 = acc[nt][0] + b0v, v01 = acc[nt][1] + b1v;
        float v10 = acc[nt][2] + b0v, v11 = acc[nt][3] + b1v;
        const int seg = cg >> 7;
        const int lc  = cg - seg * 128;
        __half* base = (seg == 0) ? g_qh : (seg == 1) ? g_kh : g_vh;
        if (seg == 0) {
            const float qs = 0.25f * LOG2E;
            v00 *= qs; v01 *= qs; v10 *= qs; v11 *= qs;
        }
        *(__half2*)(base + (size_t)r0 * DIMC + lc) = __floats2half2_rn(v00, v01);
        *(__half2*)(base + (size_t)r1 * DIMC + lc) = __floats2half2_rn(v10, v11);
    }
}

// ---------------------------------------------------------------------------
// Proj GEMM v2 (best measured): 32x64 tile, 128 threads, K=128 single pass.
// ---------------------------------------------------------------------------
struct SmemProj {
    __half Ah[32 * GS3];
    __half Al[32 * GS3];
    __half Bh[64 * GS3];
    __half Bl[64 * GS3];
};

__global__ __launch_bounds__(128, 4) void gemm_proj(const float* __restrict__ A,
                                                    const float* __restrict__ bias,
                                                    float* __restrict__ Cout)
{
    extern __shared__ char smraw[];
    SmemProj* sm = (SmemProj*)smraw;
    const int tid = threadIdx.x, warp = tid >> 5, lane = tid & 31;
    const int bm = blockIdx.x * 32, bn = blockIdx.y * 64;

    {
        const int row = tid >> 2, q = tid & 3;
        const float* Ar = A + (size_t)(bm + row) * 128 + q * 32;
        __half* ah = sm->Ah + row * GS3 + q * 32;
        __half* al = sm->Al + row * GS3 + q * 32;
#pragma unroll
        for (int j = 0; j < 8; j++) {
            float4 v = *(const float4*)(Ar + j * 4);
            u32 h0, l0, h1, l1;
            split2(v.x, v.y, h0, l0);
            split2(v.z, v.w, h1, l1);
            *(uint2*)(ah + j * 4) = make_uint2(h0, h1);
            *(uint2*)(al + j * 4) = make_uint2(l0, l1);
        }
#pragma unroll
        for (int t = 0; t < 8; t++) {
            int e = tid + t * 128;
            int rowb = e >> 4, c = e & 15;
            *(uint4*)(sm->Bh + rowb * GS3 + c * 8) = *(const uint4*)(g_wph + (size_t)(bn + rowb) * 128 + c * 8);
            *(uint4*)(sm->Bl + rowb * GS3 + c * 8) = *(const uint4*)(g_wpl + (size_t)(bn + rowb) * 128 + c * 8);
        }
    }
    __syncthreads();

    const int wm = warp >> 1, wn = warp & 1;
    const u32 aoff  = (u32)((wm * 16 + (lane & 15)) * GS3 + (lane >> 4) * 8) * 2;
    const u32 boff0 = (u32)((wn * 32 +      (lane & 15)) * GS3 + (lane >> 4) * 8) * 2;
    const u32 boff1 = (u32)((wn * 32 + 16 + (lane & 15)) * GS3 + (lane >> 4) * 8) * 2;
    const u32 ah_b  = smaddr(sm->Ah) + aoff;
    const u32 al_b  = smaddr(sm->Al) + aoff;
    const u32 bh_b0 = smaddr(sm->Bh) + boff0, bh_b1 = smaddr(sm->Bh) + boff1;
    const u32 bl_b0 = smaddr(sm->Bl) + boff0, bl_b1 = smaddr(sm->Bl) + boff1;

    float acc[4][4] = {};
#pragma unroll
    for (int ks = 0; ks < 8; ks++) {
        const u32 kb = ks * 32;
        u32 ah0, ah1, ah2, ah3;
        u32 b0, b1, b2, b3, b4, b5, b6, b7;
        ldsm_x4(ah0, ah1, ah2, ah3, ah_b + kb);
        ldsm_x4(b0, b1, b2, b3, bh_b0 + kb);
        ldsm_x4(b4, b5, b6, b7, bh_b1 + kb);
        mma16816(acc[0], ah0, ah1, ah2, ah3, b0, b2);
        mma16816(acc[1], ah0, ah1, ah2, ah3, b1, b3);
        mma16816(acc[2], ah0, ah1, ah2, ah3, b4, b6);
        mma16816(acc[3], ah0, ah1, ah2, ah3, b5, b7);
        {
            u32 al0, al1, al2, al3;
            ldsm_x4(al0, al1, al2, al3, al_b + kb);
            mma16816(acc[0], al0, al1, al2, al3, b0, b2);
            mma16816(acc[1], al0, al1, al2, al3, b1, b3);
            mma16816(acc[2], al0, al1, al2, al3, b4, b6);
            mma16816(acc[3], al0, al1, al2, al3, b5, b7);
        }
        ldsm_x4(b0, b1, b2, b3, bl_b0 + kb);
        ldsm_x4(b4, b5, b6, b7, bl_b1 + kb);
        mma16816(acc[0], ah0, ah1, ah2, ah3, b0, b2);
        mma16816(acc[1], ah0, ah1, ah2, ah3, b1, b3);
        mma16816(acc[2], ah0, ah1, ah2, ah3, b4, b6);
        mma16816(acc[3], ah0, ah1, ah2, ah3, b5, b7);
    }

    const int r0 = bm + wm * 16 + (lane >> 2);
    const int r1 = r0 + 8;
#pragma unroll
    for (int nt = 0; nt < 4; nt++) {
        const int cg = bn + wn * 32 + nt * 8 + 2 * (lane & 3);
        const float b0v = bias[cg], b1v = bias[cg + 1];
        *(float2*)(Cout + (size_t)r0 * 128 + cg) = make_float2(acc[nt][0] + b0v, acc[nt][1] + b1v);
        *(float2*)(Cout + (size_t)r1 * 128 + cg) = make_float2(acc[nt][2] + b0v, acc[nt][3] + b1v);
    }
}

// ---------------------------------------------------------------------------
// Attention v6: r10 numerics + cp.async pipelined gather.
//   group 0: K rows 0..575  -> waited before QK
//   group 1: V rows 0..287  -> waited before chunk-0 PV (overlaps QK0)
//   group 2: V rows 288..575-> waited before chunk-4 PV (overlaps chunks 0-3)
// Padded V rows (560-575) pre-zeroed; padded K rows left garbage (scores masked).
// ---------------------------------------------------------------------------
struct SmemAttn {
    __half KV[NH * RS2];
    __half Qs[10][16][24];
    int    rowmap[NH];
    unsigned short vmask[NH];
};

__global__ __launch_bounds__(320) void attn_mma(void)
{
    extern __shared__ char smraw[];
    SmemAttn* sm = (SmemAttn*)smraw;

    const int tid  = threadIdx.x;
    const int warp = tid >> 5;
    const int lane = tid & 31;

    const int hp   = blockIdx.x & 3;
    const int tile = blockIdx.x >> 2;
    const int tw   = tile % 6;
    const int th   = tile / 6;
    const int hy0  = th * 2;
    const int wx0  = tw * 8;

    const int hl   = warp / 5;
    const int dt   = warp % 5;
    const int head = hp * 2 + hl;

    // ---- phase A: rowmap + vmask + Q tiles + zero padded V rows ----
#pragma unroll
    for (int t = 0; t < 2; t++) {
        int rr = tid + t * 320;
        if (rr < NH) {
            int map = -1;
            unsigned vm = 0;
            if (rr < NREAL) {
                int d   = rr / 112;
                int rem = rr % 112;
                int ih  = rem / 14;
                int iw  = rem % 14;
                int h2  = (hy0 + ih + 21) % HH;
                int w2  = (wx0 + iw + 45) % WWID;
                map = (d * HH + h2) * WWID + w2;
                int wlo = iw - 6 < 0 ? 0 : iw - 6;
                int whi = iw < 7 ? iw : 7;
                unsigned wm = (whi >= wlo) ? ((0xFFu << wlo) & (0xFFu >> (7 - whi))) : 0u;
                unsigned m0 = (ih <= 6) ? wm : 0u;
                unsigned m1 = (ih >= 1) ? wm : 0u;
                vm = m0 | (m1 << 8);
            }
            sm->rowmap[rr] = map;
            sm->vmask[rr]  = (unsigned short)vm;
        }
    }
    {
        int r = lane >> 1, hf = lane & 1;
        int gp = ((dt * HH + hy0 + (r >> 3)) * WWID + wx0 + (r & 7));
        *(uint4*)&sm->Qs[warp][r][hf * 8] =
            *(const uint4*)(g_qh + (size_t)gp * DIMC + head * HD + hf * 8);
    }
    if (tid < 64) {   // zero V region of padded rows 560..575 (16 rows x 4 uint4)
        int row = NREAL + (tid >> 2), c = tid & 3;
        *(uint4*)&sm->KV[row * RS2 + 32 + c * 8] = make_uint4(0u, 0u, 0u, 0u);
    }
    __syncthreads();

    // ---- phase B: cp.async gather, 3 groups ----
    // group 0: K, rows 0..575 (2304 pieces / 320 thr = 8 iters)
#pragma unroll
    for (int t = 0; t < 8; t++) {
        int e = tid + t * 320;
        if (e < NH * 4) {
            int row = e >> 2, c = e & 3;
            int g = sm->rowmap[row];
            if (g >= 0)
                cpasync16(smaddr(&sm->KV[row * RS2 + c * 8]),
                          g_kh + (size_t)g * DIMC + hp * 32 + c * 8);
        }
    }
    cpasync_commit();
    // group 1: V rows 0..287 (1152 pieces)
#pragma unroll
    for (int t = 0; t < 4; t++) {
        int e = tid + t * 320;
        if (e < 288 * 4) {
            int row = e >> 2, c = e & 3;
            int g = sm->rowmap[row];
            cpasync16(smaddr(&sm->KV[row * RS2 + 32 + c * 8]),
                      g_vh + (size_t)g * DIMC + hp * 32 + c * 8);
        }
    }
    cpasync_commit();
    // group 2: V rows 288..575 (1152 pieces, skip padded)
#pragma unroll
    for (int t = 0; t < 4; t++) {
        int e = tid + t * 320;
        if (e < 288 * 4) {
            int row = 288 + (e >> 2), c = e & 3;
            int g = sm->rowmap[row];
            if (g >= 0)
                cpasync16(smaddr(&sm->KV[row * RS2 + 32 + c * 8]),
                          g_vh + (size_t)g * DIMC + hp * 32 + c * 8);
        }
    }
    cpasync_commit();

    cpasync_wait<2>();   // K arrived
    __syncthreads();

    // ---- compute: fully warp-local (r10 core) ----
    const u32 qb  = smaddr(&sm->Qs[warp][0][0]);
    const u32 kvb = smaddr(sm->KV);
    const int r0  = lane >> 2;

    u32 qa0, qa1, qa2, qa3;
    {
        int l4 = lane & 15, cg = lane >> 4;
        ldsm_x4(qa0, qa1, qa2, qa3, qb + (u32)(l4 * 24 + cg * 8) * 2);
    }

    float dacc[8];
#pragma unroll
    for (int i = 0; i < 8; i++) dacc[i] = 0.f;
    float s0 = 0.f, s1 = 0.f;

#pragma unroll
    for (int ch = 0; ch < 8; ch++) {
        const int c0 = ch * 72;
        float c[9][4];
#pragma unroll
        for (int t = 0; t < 9; t++)
            c[t][0] = c[t][1] = c[t][2] = c[t][3] = -SHIFT2;

#pragma unroll
        for (int t = 0; t < 9; t++) {
            int l4 = lane & 15;
            u32 addr = kvb + (u32)((c0 + t * 8 + (l4 & 7)) * RS2 + hl * 16 + (l4 >> 3) * 8) * 2;
            u32 b0, b1;
            ldsm_x2(b0, b1, addr);
            mma16816(c[t], qa0, qa1, qa2, qa3, b0, b1);
        }

#pragma unroll
        for (int t = 0; t < 9; t++) {
            int cA = c0 + t * 8 + 2 * (lane & 3);
            u32 mm = *(const u32*)&sm->vmask[cA];
            float e0 = ex2(c[t][0]);
            float e1 = ex2(c[t][1]);
            float e2 = ex2(c[t][2]);
            float e3 = ex2(c[t][3]);
            e0 = ((mm >> (r0)) & 1u)      ? e0 : 0.f;
            e1 = ((mm >> (16 + r0)) & 1u) ? e1 : 0.f;
            e2 = ((mm >> (8 + r0)) & 1u)  ? e2 : 0.f;
            e3 = ((mm >> (24 + r0)) & 1u) ? e3 : 0.f;
            s0 += e0 + e1;
            s1 += e2 + e3;
            c[t][0] = e0; c[t][1] = e1; c[t][2] = e2; c[t][3] = e3;
        }

        // V readiness barriers (compile-time branches under unroll)
        if (ch == 0) { cpasync_wait<1>(); __syncthreads(); }
        if (ch == 4) { cpasync_wait<0>(); __syncthreads(); }

#pragma unroll
        for (int kc = 0; kc < 4; kc++) {
            u32 a0 = packh2(c[2 * kc][0], c[2 * kc][1]);
            u32 a1 = packh2(c[2 * kc][2], c[2 * kc][3]);
            u32 a2 = packh2(c[2 * kc + 1][0], c[2 * kc + 1][1]);
            u32 a3 = packh2(c[2 * kc + 1][2], c[2 * kc + 1][3]);
            int g = lane >> 3, rr2 = lane & 7;
            int row = c0 + kc * 16 + ((g & 1) << 3) + rr2;
            u32 addr = kvb + (u32)(row * RS2 + 32 + hl * 16 + (g >> 1) * 8) * 2;
            u32 b0, b1, b2, b3;
            ldsm_x4_t(b0, b1, b2, b3, addr);
            mma16816(dacc,     a0, a1, a2, a3, b0, b1);
            mma16816(dacc + 4, a0, a1, a2, a3, b2, b3);
        }
        {
            u32 a0 = packh2(c[8][0], c[8][1]);
            u32 a1 = packh2(c[8][2], c[8][3]);
            int l4 = lane & 15;
            int row = c0 + 64 + (l4 & 7);
            u32 addr = kvb + (u32)(row * RS2 + 32 + hl * 16 + (l4 >> 3) * 8) * 2;
            u32 b0, b1;
            ldsm_x2_t(b0, b1, addr);
            mma1688(dacc,     a0, a1, b0);
            mma1688(dacc + 4, a0, a1, b1);
        }
    }

    s0 += __shfl_xor_sync(0xFFFFFFFF, s0, 1);
    s0 += __shfl_xor_sync(0xFFFFFFFF, s0, 2);
    s1 += __shfl_xor_sync(0xFFFFFFFF, s1, 1);
    s1 += __shfl_xor_sync(0xFFFFFFFF, s1, 2);
    const float inv0 = 1.f / s0, inv1 = 1.f / s1;

    const int q4 = lane & 3;
    const int gp0 = ((dt * HH + hy0 + 0) * WWID + wx0 + r0);
    const int gp1 = ((dt * HH + hy0 + 1) * WWID + wx0 + r0);
    float* o0 = g_att + (size_t)gp0 * DIMC + head * HD;
    float* o1 = g_att + (size_t)gp1 * DIMC + head * HD;
    *(float2*)(o0 + 2 * q4)     = make_float2(dacc[0] * inv0, dacc[1] * inv0);
    *(float2*)(o1 + 2 * q4)     = make_float2(dacc[2] * inv1, dacc[3] * inv1);
    *(float2*)(o0 + 8 + 2 * q4) = make_float2(dacc[4] * inv0, dacc[5] * inv0);
    *(float2*)(o1 + 8 + 2 * q4) = make_float2(dacc[6] * inv1, dacc[7] * inv1);
}

// ---------------------------------------------------------------------------
extern "C" void kernel_launch(void* const* d_in, const int* in_sizes, int n_in,
                              void* d_out, int out_size)
{
    const float* x      = (const float*)d_in[0];
    const float* qkv_w  = (const float*)d_in[1];
    const float* qkv_b  = (const float*)d_in[2];
    const float* proj_w = (const float*)d_in[3];
    const float* proj_b = (const float*)d_in[4];
    float* out = (float*)d_out;

    float* att;
    cudaGetSymbolAddress((void**)&att, g_att);

    static int attr_set = 0;
    if (!attr_set) {
        cudaFuncSetAttribute(attn_mma, cudaFuncAttributeMaxDynamicSharedMemorySize,
                             (int)sizeof(SmemAttn));
        cudaFuncSetAttribute(gemm_qkv, cudaFuncAttributeMaxDynamicSharedMemorySize,
                             (int)sizeof(SmemGemm));
        cudaFuncSetAttribute(gemm_proj, cudaFuncAttributeMaxDynamicSharedMemorySize,
                             (int)sizeof(SmemProj));
        attr_set = 1;
    }

    // 0) one-shot hi/lo split of x and weights
    split_prep<<<(200704 + 255) / 256, 256>>>(x, qkv_w, proj_w);
    // 1) QKV projection (presplit fp16 TC GEMM)
    gemm_qkv<<<dim3(NP / 64, 384 / 64), 256, sizeof(SmemGemm)>>>(qkv_b);
    // 2) neighborhood attention v6 (cp.async pipelined gather, r10 numerics)
    attn_mma<<<72 * 4, 320, sizeof(SmemAttn)>>>();
    // 3) output projection (32x64 tiles, 360 blocks)
    gemm_proj<<<dim3(NP / 32, 128 / 64), 128, sizeof(SmemProj)>>>(att, proj_b, out);
}